// round 1
// baseline (speedup 1.0000x reference)
#include <cuda_runtime.h>

#define B_   64
#define NQ   512
#define NV   1024
#define QD   768
#define VD   512
#define HIDD 512

// ---------------- scratch (device globals; no allocation allowed) ----------
__device__ float g_M[QD * VD];                 // Wq^T Wv  [768,512]
__device__ float g_a[QD];                      // Wq^T bv
__device__ float g_c[VD];                      // Wv^T bq
__device__ float g_s0;                         // bq . bv
__device__ float g_rq[B_ * NQ];                // Q.a + s0
__device__ float g_cv[B_ * NV];                // V.c
__device__ float g_QM[(size_t)B_ * NQ * VD];   // 64 MB
__device__ float g_E[(size_t)B_ * NQ * NV];    // 134 MB: exp(tanh(H))
__device__ float g_invdr[B_ * NQ];
__device__ float g_invdc[B_ * NV];
__device__ float g_wq[B_ * NQ];
__device__ float g_wv[B_ * NV];

// ---------------- small precompute: a, c, s0 -------------------------------
__global__ void compute_ac(const float* __restrict__ Wq, const float* __restrict__ Wv,
                           const float* __restrict__ bq, const float* __restrict__ bv) {
    int t = blockIdx.x * 256 + threadIdx.x;
    if (t < QD) {
        float s = 0.f;
        for (int h = 0; h < HIDD; h++) s += Wq[h * QD + t] * bv[h];
        g_a[t] = s;
    } else if (t < QD + VD) {
        int e = t - QD;
        float s = 0.f;
        for (int h = 0; h < HIDD; h++) s += Wv[h * VD + e] * bq[h];
        g_c[e] = s;
    } else if (t == QD + VD) {
        float s = 0.f;
        for (int h = 0; h < HIDD; h++) s += bq[h] * bv[h];
        g_s0 = s;
    }
}

// ---------------- warp-per-row dot: out[r] = X[r,:] . vec (+ s0) -----------
template <bool ADD_S0>
__global__ void rowdot_kernel(const float* __restrict__ X, const float* __restrict__ vec,
                              float* __restrict__ out, int K) {
    int gw = (blockIdx.x * blockDim.x + threadIdx.x) >> 5;
    int lane = threadIdx.x & 31;
    const float* row = X + (size_t)gw * K;
    float s = 0.f;
    for (int k = lane; k < K; k += 32) s += row[k] * vec[k];
#pragma unroll
    for (int o = 16; o; o >>= 1) s += __shfl_xor_sync(0xffffffffu, s, o);
    if (!lane) out[gw] = s + (ADD_S0 ? g_s0 : 0.f);
}

// ---------------- tiled SGEMM: 128x128x8, 8x8 per thread --------------------
// TRANSA: A is [K,M] (else [M,K]).  TRANSB: B is [N,K] (else [K,N]).
// EPI:    C = exp(tanh(acc + rq[bz*NQ+m] + cv[bz*NV+n]))  (fused H epilogue)
template <bool TRANSA, bool TRANSB, bool EPI>
__global__ __launch_bounds__(256)
void gemm_kernel(const float* __restrict__ Aall, const float* __restrict__ Ball,
                 float* __restrict__ Call,
                 int K, int lda, int ldb, int ldc,
                 long long strideA, long long strideB, long long strideC,
                 const float* __restrict__ rq, const float* __restrict__ cv) {
    const int BM = 128, BN = 128, BK = 8;
    const int bz = blockIdx.z;
    const float* A = Aall + (size_t)bz * strideA;
    const float* B = Ball + (size_t)bz * strideB;
    float* C = Call + (size_t)bz * strideC;
    const int m0 = blockIdx.y * BM, n0 = blockIdx.x * BN;

    __shared__ float As[BK][BM + 4];
    __shared__ float Bs[BK][BN + 4];

    const int tid = threadIdx.x;
    const int tx = tid & 15, ty = tid >> 4;

    float acc[8][8];
#pragma unroll
    for (int i = 0; i < 8; i++)
#pragma unroll
        for (int j = 0; j < 8; j++) acc[i][j] = 0.f;

    for (int k0 = 0; k0 < K; k0 += BK) {
        if (!TRANSA) {
            // A[M,K]: transpose into As
            int m = tid >> 1, k4 = (tid & 1) * 4;
            float4 av = *(const float4*)&A[(size_t)(m0 + m) * lda + k0 + k4];
            As[k4 + 0][m] = av.x; As[k4 + 1][m] = av.y;
            As[k4 + 2][m] = av.z; As[k4 + 3][m] = av.w;
        } else {
            // A[K,M]: direct
            int k = tid >> 5, m4 = (tid & 31) * 4;
            *(float4*)&As[k][m4] = *(const float4*)&A[(size_t)(k0 + k) * lda + m0 + m4];
        }
        if (!TRANSB) {
            // B[K,N]: direct
            int k = tid >> 5, n4 = (tid & 31) * 4;
            *(float4*)&Bs[k][n4] = *(const float4*)&B[(size_t)(k0 + k) * ldb + n0 + n4];
        } else {
            // B[N,K]: transpose into Bs
            int n = tid >> 1, k4 = (tid & 1) * 4;
            float4 bvv = *(const float4*)&B[(size_t)(n0 + n) * ldb + k0 + k4];
            Bs[k4 + 0][n] = bvv.x; Bs[k4 + 1][n] = bvv.y;
            Bs[k4 + 2][n] = bvv.z; Bs[k4 + 3][n] = bvv.w;
        }
        __syncthreads();
#pragma unroll
        for (int k = 0; k < BK; k++) {
            float4 a0 = *(const float4*)&As[k][ty * 8];
            float4 a1 = *(const float4*)&As[k][ty * 8 + 4];
            float4 b0 = *(const float4*)&Bs[k][tx * 8];
            float4 b1 = *(const float4*)&Bs[k][tx * 8 + 4];
            float ar[8] = {a0.x, a0.y, a0.z, a0.w, a1.x, a1.y, a1.z, a1.w};
            float br[8] = {b0.x, b0.y, b0.z, b0.w, b1.x, b1.y, b1.z, b1.w};
#pragma unroll
            for (int i = 0; i < 8; i++)
#pragma unroll
                for (int j = 0; j < 8; j++) acc[i][j] += ar[i] * br[j];
        }
        __syncthreads();
    }

#pragma unroll
    for (int i = 0; i < 8; i++) {
        int m = m0 + ty * 8 + i;
        float radd = 0.f;
        if (EPI) radd = rq[bz * NQ + m];
        float vals[8];
#pragma unroll
        for (int j = 0; j < 8; j++) {
            float x = acc[i][j];
            if (EPI) {
                int n = n0 + tx * 8 + j;
                x = __expf(tanhf(x + radd + cv[bz * NV + n]));
            }
            vals[j] = x;
        }
        float4* cptr = (float4*)&C[(size_t)m * ldc + n0 + tx * 8];
        cptr[0] = make_float4(vals[0], vals[1], vals[2], vals[3]);
        cptr[1] = make_float4(vals[4], vals[5], vals[6], vals[7]);
    }
}

// ---------------- softmax reductions ----------------------------------------
__global__ void denomr_kernel() {  // invdr[r] = 1 / sum_v E[r,v]
    int gw = (blockIdx.x * blockDim.x + threadIdx.x) >> 5;
    int lane = threadIdx.x & 31;
    const float* row = g_E + (size_t)gw * NV;
    float s = 0.f;
#pragma unroll 8
    for (int v = lane; v < NV; v += 32) s += row[v];
#pragma unroll
    for (int o = 16; o; o >>= 1) s += __shfl_xor_sync(0xffffffffu, s, o);
    if (!lane) g_invdr[gw] = 1.0f / s;
}

__global__ void denomc_kernel() {  // invdc[b,v] = 1 / sum_q E[b,q,v]
    int b = blockIdx.y;
    int v = blockIdx.x * 256 + threadIdx.x;
    const float* Eb = g_E + (size_t)b * NQ * NV + v;
    float s = 0.f;
#pragma unroll 8
    for (int q = 0; q < NQ; q++) s += Eb[(size_t)q * NV];
    g_invdc[b * NV + v] = 1.0f / s;
}

__global__ void wq_kernel() {  // wq[b,q] = sum_v E[b,q,v] * invdc[b,v]
    int gw = (blockIdx.x * blockDim.x + threadIdx.x) >> 5;
    int lane = threadIdx.x & 31;
    int b = gw >> 9;  // / NQ
    const float* row = g_E + (size_t)gw * NV;
    const float* dc = g_invdc + b * NV;
    float s = 0.f;
#pragma unroll 8
    for (int v = lane; v < NV; v += 32) s += row[v] * dc[v];
#pragma unroll
    for (int o = 16; o; o >>= 1) s += __shfl_xor_sync(0xffffffffu, s, o);
    if (!lane) g_wq[gw] = s;
}

__global__ void wv_kernel() {  // wv[b,v] = sum_q E[b,q,v] * invdr[b,q]
    int b = blockIdx.y;
    int v = blockIdx.x * 256 + threadIdx.x;
    const float* Eb = g_E + (size_t)b * NQ * NV + v;
    const float* dr = g_invdr + b * NQ;
    float s = 0.f;
#pragma unroll 8
    for (int q = 0; q < NQ; q++) s += Eb[(size_t)q * NV] * dr[q];
    g_wv[b * NV + v] = s;
}

// ---------------- final pools -----------------------------------------------
__global__ void vhat_kernel(const float* __restrict__ V, float* __restrict__ out) {
    int b = blockIdx.x, d = threadIdx.x;  // 512 threads
    const float* Vb = V + (size_t)b * NV * VD;
    const float* wv = g_wv + b * NV;
    float s = 0.f;
#pragma unroll 4
    for (int v = 0; v < NV; v++) s += wv[v] * Vb[(size_t)v * VD + d];
    out[b * VD + d] = s;
}

__global__ void qhat_kernel(const float* __restrict__ Q, float* __restrict__ out) {
    int b = blockIdx.x, d = threadIdx.x;  // 768 threads
    const float* Qb = Q + (size_t)b * NQ * QD;
    const float* wq = g_wq + b * NQ;
    float s = 0.f;
#pragma unroll 4
    for (int q = 0; q < NQ; q++) s += wq[q] * Qb[(size_t)q * QD + d];
    out[B_ * VD + b * QD + d] = s;
}

// ---------------- launch -----------------------------------------------------
extern "C" void kernel_launch(void* const* d_in, const int* in_sizes, int n_in,
                              void* d_out, int out_size) {
    const float* V  = (const float*)d_in[0];  // [64,1024,512]
    const float* Q  = (const float*)d_in[1];  // [64,512,768]
    const float* Wq = (const float*)d_in[2];  // [512,768]
    const float* bq = (const float*)d_in[3];  // [512]
    const float* Wv = (const float*)d_in[4];  // [512,512]
    const float* bv = (const float*)d_in[5];  // [512]
    float* out = (float*)d_out;               // [64*512 v_hat | 64*768 q_hat]

    float *pM, *pa, *pc, *prq, *pcv, *pQM, *pE;
    cudaGetSymbolAddress((void**)&pM, g_M);
    cudaGetSymbolAddress((void**)&pa, g_a);
    cudaGetSymbolAddress((void**)&pc, g_c);
    cudaGetSymbolAddress((void**)&prq, g_rq);
    cudaGetSymbolAddress((void**)&pcv, g_cv);
    cudaGetSymbolAddress((void**)&pQM, g_QM);
    cudaGetSymbolAddress((void**)&pE, g_E);

    // 1) a, c, s0
    compute_ac<<<6, 256>>>(Wq, Wv, bq, bv);
    // 2) M = Wq^T Wv  (TN GEMM: M=768, N=512, K=512)
    gemm_kernel<true, false, false><<<dim3(VD / 128, QD / 128, 1), 256>>>(
        Wq, Wv, pM, HIDD, QD, VD, VD, 0, 0, 0, nullptr, nullptr);
    // 3) rq = Q.a + s0 ; cv = V.c
    rowdot_kernel<true><<<(B_ * NQ) / 8, 256>>>(Q, pa, prq, QD);
    rowdot_kernel<false><<<(B_ * NV) / 8, 256>>>(V, pc, pcv, VD);
    // 4) QM = Q @ M  (NN GEMM: M=32768, N=512, K=768)
    gemm_kernel<false, false, false><<<dim3(VD / 128, (B_ * NQ) / 128, 1), 256>>>(
        Q, pM, pQM, QD, QD, VD, VD, 0, 0, 0, nullptr, nullptr);
    // 5) E = exp(tanh(QM @ V^T + rq + cv))  batched NT GEMM: M=512, N=1024, K=512
    gemm_kernel<false, true, true><<<dim3(NV / 128, NQ / 128, B_), 256>>>(
        pQM, V, pE, HIDD, HIDD, VD, NV,
        (long long)NQ * HIDD, (long long)NV * VD, (long long)NQ * NV, prq, pcv);
    // 6) softmax denominators (both axes), then pooled softmax weights
    denomr_kernel<<<(B_ * NQ) / 8, 256>>>();
    denomc_kernel<<<dim3(NV / 256, B_), 256>>>();
    wq_kernel<<<(B_ * NQ) / 8, 256>>>();
    wv_kernel<<<dim3(NV / 256, B_), 256>>>();
    // 7) pools
    vhat_kernel<<<B_, VD>>>(V, out);
    qhat_kernel<<<B_, QD>>>(Q, out);
}

// round 4
// speedup vs baseline: 1.5027x; 1.5027x over previous
#include <cuda_runtime.h>
#include <cuda_bf16.h>
#include <cstdint>

#define B_   64
#define NQ   512
#define NV   1024
#define QD   768
#define VD   512
#define HIDD 512

// ---------------- scratch (device globals; no allocation allowed) ----------
__device__ float g_MT[VD * QD];                // MT[v,q] = sum_h Wv[h,v] Wq[h,q]
__device__ float g_a[QD];
__device__ float g_c[VD];
__device__ float g_s0;
__device__ float g_rq[B_ * NQ];
__device__ float g_cv[B_ * NV];
__device__ __align__(16) __nv_bfloat16 g_Qh[(size_t)B_ * NQ * QD];
__device__ __align__(16) __nv_bfloat16 g_Ql[(size_t)B_ * NQ * QD];
__device__ __align__(16) __nv_bfloat16 g_Vh[(size_t)B_ * NV * VD];
__device__ __align__(16) __nv_bfloat16 g_Vl[(size_t)B_ * NV * VD];
__device__ __align__(16) __nv_bfloat16 g_MTh[VD * QD];
__device__ __align__(16) __nv_bfloat16 g_MTl[VD * QD];
__device__ __align__(16) __nv_bfloat16 g_QMh[(size_t)B_ * NQ * VD];
__device__ __align__(16) __nv_bfloat16 g_QMl[(size_t)B_ * NQ * VD];
__device__ float g_E[(size_t)B_ * NQ * NV];
__device__ float g_invdr[B_ * NQ];
__device__ float g_invdc[B_ * NV];
__device__ float g_wq[B_ * NQ];
__device__ float g_wv[B_ * NV];

// ---------------- PTX helpers (sm_80+ features only) ------------------------
__device__ __forceinline__ uint32_t smem_u32(const void* p) {
    uint32_t a;
    asm("{ .reg .u64 t; cvta.to.shared.u64 t, %1; cvt.u32.u64 %0, t; }" : "=r"(a) : "l"(p));
    return a;
}
__device__ __forceinline__ void cp16(uint32_t s, const void* g) {
    asm volatile("cp.async.cg.shared.global [%0], [%1], 16;" :: "r"(s), "l"(g));
}
__device__ __forceinline__ void cp_commit() { asm volatile("cp.async.commit_group;" ::: "memory"); }
__device__ __forceinline__ void cp_wait1()  { asm volatile("cp.async.wait_group 1;" ::: "memory"); }

__device__ __forceinline__ void ldm4(uint32_t a, uint32_t& r0, uint32_t& r1,
                                     uint32_t& r2, uint32_t& r3) {
    asm volatile("ldmatrix.sync.aligned.m8n8.x4.shared.b16 {%0,%1,%2,%3}, [%4];"
                 : "=r"(r0), "=r"(r1), "=r"(r2), "=r"(r3) : "r"(a));
}
__device__ __forceinline__ void mma16816(float& c0, float& c1, float& c2, float& c3,
                                         uint32_t a0, uint32_t a1, uint32_t a2, uint32_t a3,
                                         uint32_t b0, uint32_t b1) {
    asm volatile("mma.sync.aligned.m16n8k16.row.col.f32.bf16.bf16.f32 "
                 "{%0,%1,%2,%3}, {%4,%5,%6,%7}, {%8,%9}, {%0,%1,%2,%3};"
                 : "+f"(c0), "+f"(c1), "+f"(c2), "+f"(c3)
                 : "r"(a0), "r"(a1), "r"(a2), "r"(a3), "r"(b0), "r"(b1));
}

// ---------------- small precompute: a, c, s0 -------------------------------
__global__ void compute_ac(const float* __restrict__ Wq, const float* __restrict__ Wv,
                           const float* __restrict__ bq, const float* __restrict__ bv) {
    int t = blockIdx.x * 256 + threadIdx.x;
    if (t < QD) {
        float s = 0.f;
        for (int h = 0; h < HIDD; h++) s += Wq[h * QD + t] * bv[h];
        g_a[t] = s;
    } else if (t < QD + VD) {
        int e = t - QD;
        float s = 0.f;
        for (int h = 0; h < HIDD; h++) s += Wv[h * VD + e] * bq[h];
        g_c[e] = s;
    } else if (t == QD + VD) {
        float s = 0.f;
        for (int h = 0; h < HIDD; h++) s += bq[h] * bv[h];
        g_s0 = s;
    }
}

// ---------------- warp-per-row dot ------------------------------------------
template <bool ADD_S0>
__global__ void rowdot_kernel(const float* __restrict__ X, const float* __restrict__ vec,
                              float* __restrict__ out, int K) {
    int gw = (blockIdx.x * blockDim.x + threadIdx.x) >> 5;
    int lane = threadIdx.x & 31;
    const float* row = X + (size_t)gw * K;
    float s = 0.f;
    for (int k = lane; k < K; k += 32) s += row[k] * vec[k];
#pragma unroll
    for (int o = 16; o; o >>= 1) s += __shfl_xor_sync(0xffffffffu, s, o);
    if (!lane) out[gw] = s + (ADD_S0 ? g_s0 : 0.f);
}

// ---------------- fp32 GEMM (only for tiny MT = Wv^T Wq) --------------------
__global__ __launch_bounds__(256)
void gemm_tn_kernel(const float* __restrict__ A, const float* __restrict__ B,
                    float* __restrict__ C, int K, int lda, int ldb, int ldc) {
    const int BM = 128, BN = 128, BK = 8;
    const int m0 = blockIdx.y * BM, n0 = blockIdx.x * BN;
    __shared__ float As[BK][BM + 4];
    __shared__ float Bs[BK][BN + 4];
    const int tid = threadIdx.x;
    const int tx = tid & 15, ty = tid >> 4;
    float acc[8][8];
#pragma unroll
    for (int i = 0; i < 8; i++)
#pragma unroll
        for (int j = 0; j < 8; j++) acc[i][j] = 0.f;
    for (int k0 = 0; k0 < K; k0 += BK) {
        {
            int k = tid >> 5, m4 = (tid & 31) * 4;
            *(float4*)&As[k][m4] = *(const float4*)&A[(size_t)(k0 + k) * lda + m0 + m4];
        }
        {
            int k = tid >> 5, n4 = (tid & 31) * 4;
            *(float4*)&Bs[k][n4] = *(const float4*)&B[(size_t)(k0 + k) * ldb + n0 + n4];
        }
        __syncthreads();
#pragma unroll
        for (int k = 0; k < BK; k++) {
            float4 a0 = *(const float4*)&As[k][ty * 8];
            float4 a1 = *(const float4*)&As[k][ty * 8 + 4];
            float4 b0 = *(const float4*)&Bs[k][tx * 8];
            float4 b1 = *(const float4*)&Bs[k][tx * 8 + 4];
            float ar[8] = {a0.x, a0.y, a0.z, a0.w, a1.x, a1.y, a1.z, a1.w};
            float br[8] = {b0.x, b0.y, b0.z, b0.w, b1.x, b1.y, b1.z, b1.w};
#pragma unroll
            for (int i = 0; i < 8; i++)
#pragma unroll
                for (int j = 0; j < 8; j++) acc[i][j] += ar[i] * br[j];
        }
        __syncthreads();
    }
#pragma unroll
    for (int i = 0; i < 8; i++) {
        int m = m0 + ty * 8 + i;
        float4* cptr = (float4*)&C[(size_t)m * ldc + n0 + tx * 8];
        cptr[0] = make_float4(acc[i][0], acc[i][1], acc[i][2], acc[i][3]);
        cptr[1] = make_float4(acc[i][4], acc[i][5], acc[i][6], acc[i][7]);
    }
}

// ---------------- fp32 -> bf16 hi/lo split -----------------------------------
__global__ void split_kernel(const float* __restrict__ x, __nv_bfloat16* __restrict__ hi,
                             __nv_bfloat16* __restrict__ lo, int n4) {
    int i = blockIdx.x * 256 + threadIdx.x;
    if (i >= n4) return;
    float4 v = ((const float4*)x)[i];
    __nv_bfloat16 h0 = __float2bfloat16(v.x), h1 = __float2bfloat16(v.y);
    __nv_bfloat16 h2 = __float2bfloat16(v.z), h3 = __float2bfloat16(v.w);
    __nv_bfloat162* H = (__nv_bfloat162*)hi;
    __nv_bfloat162* L = (__nv_bfloat162*)lo;
    H[2 * i]     = __halves2bfloat162(h0, h1);
    H[2 * i + 1] = __halves2bfloat162(h2, h3);
    L[2 * i]     = __halves2bfloat162(__float2bfloat16(v.x - __bfloat162float(h0)),
                                      __float2bfloat16(v.y - __bfloat162float(h1)));
    L[2 * i + 1] = __halves2bfloat162(__float2bfloat16(v.z - __bfloat162float(h2)),
                                      __float2bfloat16(v.w - __bfloat162float(h3)));
}

// ---------------- mma.sync bf16x3 GEMM, 128x128x32, double-buffered ----------
// D[m,n] = sum over 3 passes of A_p[m,k]*B_p[n,k]; A,B K-major bf16 hi/lo.
// SMEM rows padded to 80B: conflict-free ldmatrix (bank starts 20r mod 32).
#define STG_BYTES 20480   // A tile 128*80 + B tile 128*80

__device__ __forceinline__ void load_stage(uint32_t sb, const __nv_bfloat16* pa,
                                           const __nv_bfloat16* pb, int m0, int n0,
                                           int kk, int K, int r, int c) {
    const __nv_bfloat16* ga = pa + (size_t)(m0 + r) * K + kk + c * 8;
    cp16(sb + r * 80 + c * 16, ga);
    cp16(sb + (r + 64) * 80 + c * 16, ga + (size_t)64 * K);
    const __nv_bfloat16* gb = pb + (size_t)(n0 + r) * K + kk + c * 8;
    cp16(sb + 10240 + r * 80 + c * 16, gb);
    cp16(sb + 10240 + (r + 64) * 80 + c * 16, gb + (size_t)64 * K);
}

template <bool EPI>
__global__ __launch_bounds__(256, 1)
void mma_gemm(const __nv_bfloat16* __restrict__ Ah, const __nv_bfloat16* __restrict__ Al,
              const __nv_bfloat16* __restrict__ Bh, const __nv_bfloat16* __restrict__ Bl,
              int K, long long sA, long long sB,
              __nv_bfloat16* __restrict__ Chi, __nv_bfloat16* __restrict__ Clo, int ldc,
              float* __restrict__ E, const float* __restrict__ rq, const float* __restrict__ cv) {
    __shared__ __align__(128) uint8_t smbuf[2][STG_BYTES];
    const int tid = threadIdx.x, lid = tid & 31, wid = tid >> 5;
    const int wm = wid >> 2, wn = wid & 3;   // 2 x 4 warp grid
    const int m0 = blockIdx.y * 128, n0 = blockIdx.x * 128, bz = blockIdx.z;
    Ah += (size_t)bz * sA; Al += (size_t)bz * sA;
    Bh += (size_t)bz * sB; Bl += (size_t)bz * sB;

    const int kpp = K / 32, T = 3 * kpp;
    const int lr = tid >> 2, lc = tid & 3;   // loader row/chunk

    float acc[4][4][4] = {};
    uint32_t sbase[2] = { smem_u32(smbuf[0]), smem_u32(smbuf[1]) };

    // prologue: stages 0,1
#pragma unroll
    for (int i = 0; i < 2; i++) {
        int p = i / kpp, kk = (i % kpp) * 32;
        load_stage(sbase[i & 1], (p == 2) ? Al : Ah, (p == 1) ? Bl : Bh,
                   m0, n0, kk, K, lr, lc);
        cp_commit();
    }

    for (int i = 0; i < T; i++) {
        cp_wait1();
        __syncthreads();
        uint32_t sb = sbase[i & 1];

        uint32_t Af[2][4][4], Bf[2][2][4];
#pragma unroll
        for (int ks = 0; ks < 2; ks++) {
#pragma unroll
            for (int mf = 0; mf < 4; mf++) {
                int row = wm * 64 + mf * 16 + (lid & 15);
                int ch = ks * 2 + (lid >> 4);
                ldm4(sb + row * 80 + ch * 16,
                     Af[ks][mf][0], Af[ks][mf][1], Af[ks][mf][2], Af[ks][mf][3]);
            }
#pragma unroll
            for (int np = 0; np < 2; np++) {
                int g = lid >> 3;
                int row = wn * 32 + np * 16 + ((g >> 1) << 3) + (lid & 7);
                int ch = ks * 2 + (g & 1);
                ldm4(sb + 10240 + row * 80 + ch * 16,
                     Bf[ks][np][0], Bf[ks][np][1], Bf[ks][np][2], Bf[ks][np][3]);
            }
        }
        __syncthreads();
        if (i + 2 < T) {
            int j = i + 2, p = j / kpp, kk = (j % kpp) * 32;
            load_stage(sbase[j & 1], (p == 2) ? Al : Ah, (p == 1) ? Bl : Bh,
                       m0, n0, kk, K, lr, lc);
        }
        cp_commit();
#pragma unroll
        for (int ks = 0; ks < 2; ks++)
#pragma unroll
            for (int mf = 0; mf < 4; mf++)
#pragma unroll
                for (int nf = 0; nf < 4; nf++) {
                    uint32_t b0 = Bf[ks][nf >> 1][(nf & 1) * 2];
                    uint32_t b1 = Bf[ks][nf >> 1][(nf & 1) * 2 + 1];
                    mma16816(acc[mf][nf][0], acc[mf][nf][1], acc[mf][nf][2], acc[mf][nf][3],
                             Af[ks][mf][0], Af[ks][mf][1], Af[ks][mf][2], Af[ks][mf][3],
                             b0, b1);
                }
    }

    // epilogue
    const int gr = lid >> 2, gc = (lid & 3) * 2;
#pragma unroll
    for (int mf = 0; mf < 4; mf++) {
        int m = m0 + wm * 64 + mf * 16 + gr;
        float r0v = 0.f, r1v = 0.f;
        if (EPI) { r0v = rq[bz * NQ + m]; r1v = rq[bz * NQ + m + 8]; }
#pragma unroll
        for (int nf = 0; nf < 4; nf++) {
            int n = n0 + wn * 32 + nf * 8 + gc;
            float c0 = acc[mf][nf][0], c1 = acc[mf][nf][1];
            float c2 = acc[mf][nf][2], c3 = acc[mf][nf][3];
            if (EPI) {
                float cv0 = cv[bz * NV + n], cv1 = cv[bz * NV + n + 1];
                size_t e0 = (size_t)bz * NQ * NV + (size_t)m * NV + n;
                float2 o0, o1;
                o0.x = __expf(tanhf(c0 + r0v + cv0));
                o0.y = __expf(tanhf(c1 + r0v + cv1));
                o1.x = __expf(tanhf(c2 + r1v + cv0));
                o1.y = __expf(tanhf(c3 + r1v + cv1));
                *(float2*)(E + e0) = o0;
                *(float2*)(E + e0 + (size_t)8 * NV) = o1;
            } else {
                size_t p0 = (size_t)m * ldc + n;
                size_t p1 = (size_t)(m + 8) * ldc + n;
                __nv_bfloat16 h0 = __float2bfloat16(c0), h1 = __float2bfloat16(c1);
                __nv_bfloat16 h2 = __float2bfloat16(c2), h3 = __float2bfloat16(c3);
                *(__nv_bfloat162*)(Chi + p0) = __halves2bfloat162(h0, h1);
                *(__nv_bfloat162*)(Chi + p1) = __halves2bfloat162(h2, h3);
                *(__nv_bfloat162*)(Clo + p0) = __halves2bfloat162(
                    __float2bfloat16(c0 - __bfloat162float(h0)),
                    __float2bfloat16(c1 - __bfloat162float(h1)));
                *(__nv_bfloat162*)(Clo + p1) = __halves2bfloat162(
                    __float2bfloat16(c2 - __bfloat162float(h2)),
                    __float2bfloat16(c3 - __bfloat162float(h3)));
            }
        }
    }
}

// ---------------- softmax reductions ----------------------------------------
__global__ void denomr_kernel() {
    int gw = (blockIdx.x * blockDim.x + threadIdx.x) >> 5;
    int lane = threadIdx.x & 31;
    const float* row = g_E + (size_t)gw * NV;
    float s = 0.f;
#pragma unroll 8
    for (int v = lane; v < NV; v += 32) s += row[v];
#pragma unroll
    for (int o = 16; o; o >>= 1) s += __shfl_xor_sync(0xffffffffu, s, o);
    if (!lane) g_invdr[gw] = 1.0f / s;
}

__global__ void denomc_kernel() {
    int b = blockIdx.y;
    int v = blockIdx.x * 256 + threadIdx.x;
    const float* Eb = g_E + (size_t)b * NQ * NV + v;
    float s = 0.f;
#pragma unroll 8
    for (int q = 0; q < NQ; q++) s += Eb[(size_t)q * NV];
    g_invdc[b * NV + v] = 1.0f / s;
}

__global__ void wq_kernel() {
    int gw = (blockIdx.x * blockDim.x + threadIdx.x) >> 5;
    int lane = threadIdx.x & 31;
    int b = gw >> 9;
    const float* row = g_E + (size_t)gw * NV;
    const float* dc = g_invdc + b * NV;
    float s = 0.f;
#pragma unroll 8
    for (int v = lane; v < NV; v += 32) s += row[v] * dc[v];
#pragma unroll
    for (int o = 16; o; o >>= 1) s += __shfl_xor_sync(0xffffffffu, s, o);
    if (!lane) g_wq[gw] = s;
}

__global__ void wv_kernel() {
    int b = blockIdx.y;
    int v = blockIdx.x * 256 + threadIdx.x;
    const float* Eb = g_E + (size_t)b * NQ * NV + v;
    const float* dr = g_invdr + b * NQ;
    float s = 0.f;
#pragma unroll 8
    for (int q = 0; q < NQ; q++) s += Eb[(size_t)q * NV] * dr[q];
    g_wv[b * NV + v] = s;
}

// ---------------- final pools -----------------------------------------------
__global__ void vhat_kernel(const float* __restrict__ V, float* __restrict__ out) {
    int b = blockIdx.x, d = threadIdx.x;
    const float* Vb = V + (size_t)b * NV * VD;
    const float* wv = g_wv + b * NV;
    float s = 0.f;
#pragma unroll 4
    for (int v = 0; v < NV; v++) s += wv[v] * Vb[(size_t)v * VD + d];
    out[b * VD + d] = s;
}

__global__ void qhat_kernel(const float* __restrict__ Q, float* __restrict__ out) {
    int b = blockIdx.x, d = threadIdx.x;
    const float* Qb = Q + (size_t)b * NQ * QD;
    const float* wq = g_wq + b * NQ;
    float s = 0.f;
#pragma unroll 4
    for (int q = 0; q < NQ; q++) s += wq[q] * Qb[(size_t)q * QD + d];
    out[B_ * VD + b * QD + d] = s;
}

// ---------------- launch -----------------------------------------------------
extern "C" void kernel_launch(void* const* d_in, const int* in_sizes, int n_in,
                              void* d_out, int out_size) {
    const float* V  = (const float*)d_in[0];
    const float* Q  = (const float*)d_in[1];
    const float* Wq = (const float*)d_in[2];
    const float* bq = (const float*)d_in[3];
    const float* Wv = (const float*)d_in[4];
    const float* bv = (const float*)d_in[5];
    float* out = (float*)d_out;

    float *pMT, *pa, *pc, *prq, *pcv, *pE;
    __nv_bfloat16 *pQh, *pQl, *pVh, *pVl, *pMTh, *pMTl, *pQMh, *pQMl;
    cudaGetSymbolAddress((void**)&pMT, g_MT);
    cudaGetSymbolAddress((void**)&pa, g_a);
    cudaGetSymbolAddress((void**)&pc, g_c);
    cudaGetSymbolAddress((void**)&prq, g_rq);
    cudaGetSymbolAddress((void**)&pcv, g_cv);
    cudaGetSymbolAddress((void**)&pE, g_E);
    cudaGetSymbolAddress((void**)&pQh, g_Qh);
    cudaGetSymbolAddress((void**)&pQl, g_Ql);
    cudaGetSymbolAddress((void**)&pVh, g_Vh);
    cudaGetSymbolAddress((void**)&pVl, g_Vl);
    cudaGetSymbolAddress((void**)&pMTh, g_MTh);
    cudaGetSymbolAddress((void**)&pMTl, g_MTl);
    cudaGetSymbolAddress((void**)&pQMh, g_QMh);
    cudaGetSymbolAddress((void**)&pQMl, g_QMl);

    // 1) a, c, s0
    compute_ac<<<6, 256>>>(Wq, Wv, bq, bv);
    // 2) MT[v,q] = sum_h Wv[h,v] * Wq[h,q]   (fp32, tiny)
    gemm_tn_kernel<<<dim3(QD / 128, VD / 128, 1), 256>>>(Wv, Wq, pMT, HIDD, VD, QD, QD);
    // 3) hi/lo splits
    split_kernel<<<(VD * QD / 4 + 255) / 256, 256>>>(pMT, pMTh, pMTl, VD * QD / 4);
    split_kernel<<<(B_ * NQ * QD / 4 + 255) / 256, 256>>>(Q, pQh, pQl, B_ * NQ * QD / 4);
    split_kernel<<<(B_ * NV * VD / 4 + 255) / 256, 256>>>(V, pVh, pVl, B_ * NV * VD / 4);
    // 4) rq = Q.a + s0 ; cv = V.c
    rowdot_kernel<true><<<(B_ * NQ) / 8, 256>>>(Q, pa, prq, QD);
    rowdot_kernel<false><<<(B_ * NV) / 8, 256>>>(V, pc, pcv, VD);
    // 5) QM = Q @ MT^T  (mma.sync bf16x3), epilogue writes QM hi/lo
    mma_gemm<false><<<dim3(VD / 128, (B_ * NQ) / 128, 1), 256>>>(
        pQh, pQl, pMTh, pMTl, QD, 0, 0, pQMh, pQMl, VD, nullptr, nullptr, nullptr);
    // 6) E = exp(tanh(QM @ V^T + rq + cv))  (mma.sync bf16x3, batched)
    mma_gemm<true><<<dim3(NV / 128, NQ / 128, B_), 256>>>(
        pQMh, pQMl, pVh, pVl, VD, (long long)NQ * VD, (long long)NV * VD,
        nullptr, nullptr, 0, pE, prq, pcv);
    // 7) softmax denominators, pooled softmax weights
    denomr_kernel<<<(B_ * NQ) / 8, 256>>>();
    denomc_kernel<<<dim3(NV / 256, B_), 256>>>();
    wq_kernel<<<(B_ * NQ) / 8, 256>>>();
    wv_kernel<<<dim3(NV / 256, B_), 256>>>();
    // 8) pools
    vhat_kernel<<<B_, VD>>>(V, out);
    qhat_kernel<<<B_, QD>>>(Q, out);
}

// round 5
// speedup vs baseline: 2.3178x; 1.5424x over previous
#include <cuda_runtime.h>
#include <cuda_fp16.h>
#include <cstdint>

#define B_   64
#define NQ   512
#define NV   1024
#define QD   768
#define VD   512
#define HIDD 512

// ---------------- scratch (device globals; no allocation allowed) ----------
__device__ float g_MT[VD * QD];                // MT[v,q] = sum_h Wv[h,v] Wq[h,q]
__device__ float g_a[QD];
__device__ float g_c[VD];
__device__ float g_s0;
__device__ float g_rq[B_ * NQ];
__device__ float g_cv[B_ * NV];
__device__ __align__(16) __half g_Qf[(size_t)B_ * NQ * QD];
__device__ __align__(16) __half g_Vf[(size_t)B_ * NV * VD];
__device__ __align__(16) __half g_MTf[VD * QD];
__device__ __align__(16) __half g_QMf[(size_t)B_ * NQ * VD];
__device__ float g_E[(size_t)B_ * NQ * NV];
__device__ float g_invdr[B_ * NQ];
__device__ float g_invdc[B_ * NV];
__device__ float g_wq[B_ * NQ];
__device__ float g_wv[B_ * NV];

// ---------------- PTX helpers (sm_80+ features only) ------------------------
__device__ __forceinline__ uint32_t smem_u32(const void* p) {
    uint32_t a;
    asm("{ .reg .u64 t; cvta.to.shared.u64 t, %1; cvt.u32.u64 %0, t; }" : "=r"(a) : "l"(p));
    return a;
}
__device__ __forceinline__ void cp16(uint32_t s, const void* g) {
    asm volatile("cp.async.cg.shared.global [%0], [%1], 16;" :: "r"(s), "l"(g));
}
__device__ __forceinline__ void cp_commit() { asm volatile("cp.async.commit_group;" ::: "memory"); }
__device__ __forceinline__ void cp_wait1()  { asm volatile("cp.async.wait_group 1;" ::: "memory"); }

__device__ __forceinline__ void ldm4(uint32_t a, uint32_t& r0, uint32_t& r1,
                                     uint32_t& r2, uint32_t& r3) {
    asm volatile("ldmatrix.sync.aligned.m8n8.x4.shared.b16 {%0,%1,%2,%3}, [%4];"
                 : "=r"(r0), "=r"(r1), "=r"(r2), "=r"(r3) : "r"(a));
}
__device__ __forceinline__ void mma16816(float& c0, float& c1, float& c2, float& c3,
                                         uint32_t a0, uint32_t a1, uint32_t a2, uint32_t a3,
                                         uint32_t b0, uint32_t b1) {
    asm volatile("mma.sync.aligned.m16n8k16.row.col.f32.f16.f16.f32 "
                 "{%0,%1,%2,%3}, {%4,%5,%6,%7}, {%8,%9}, {%0,%1,%2,%3};"
                 : "+f"(c0), "+f"(c1), "+f"(c2), "+f"(c3)
                 : "r"(a0), "r"(a1), "r"(a2), "r"(a3), "r"(b0), "r"(b1));
}

// ---------------- small precompute: a, c, s0 -------------------------------
__global__ void compute_ac(const float* __restrict__ Wq, const float* __restrict__ Wv,
                           const float* __restrict__ bq, const float* __restrict__ bv) {
    int t = blockIdx.x * 256 + threadIdx.x;
    if (t < QD) {
        float s = 0.f;
        for (int h = 0; h < HIDD; h++) s += Wq[h * QD + t] * bv[h];
        g_a[t] = s;
    } else if (t < QD + VD) {
        int e = t - QD;
        float s = 0.f;
        for (int h = 0; h < HIDD; h++) s += Wv[h * VD + e] * bq[h];
        g_c[e] = s;
    } else if (t == QD + VD) {
        float s = 0.f;
        for (int h = 0; h < HIDD; h++) s += bq[h] * bv[h];
        g_s0 = s;
    }
}

// ---------------- warp-per-row dot ------------------------------------------
template <bool ADD_S0>
__global__ void rowdot_kernel(const float* __restrict__ X, const float* __restrict__ vec,
                              float* __restrict__ out, int K) {
    int gw = (blockIdx.x * blockDim.x + threadIdx.x) >> 5;
    int lane = threadIdx.x & 31;
    const float* row = X + (size_t)gw * K;
    float s = 0.f;
    for (int k = lane; k < K; k += 32) s += row[k] * vec[k];
#pragma unroll
    for (int o = 16; o; o >>= 1) s += __shfl_xor_sync(0xffffffffu, s, o);
    if (!lane) out[gw] = s + (ADD_S0 ? g_s0 : 0.f);
}

// ---------------- fp32 GEMM (only for tiny MT = Wv^T Wq) --------------------
__global__ __launch_bounds__(256)
void gemm_tn_kernel(const float* __restrict__ A, const float* __restrict__ B,
                    float* __restrict__ C, int K, int lda, int ldb, int ldc) {
    const int BM = 128, BN = 128, BK = 8;
    const int m0 = blockIdx.y * BM, n0 = blockIdx.x * BN;
    __shared__ float As[BK][BM + 4];
    __shared__ float Bs[BK][BN + 4];
    const int tid = threadIdx.x;
    const int tx = tid & 15, ty = tid >> 4;
    float acc[8][8];
#pragma unroll
    for (int i = 0; i < 8; i++)
#pragma unroll
        for (int j = 0; j < 8; j++) acc[i][j] = 0.f;
    for (int k0 = 0; k0 < K; k0 += BK) {
        {
            int k = tid >> 5, m4 = (tid & 31) * 4;
            *(float4*)&As[k][m4] = *(const float4*)&A[(size_t)(k0 + k) * lda + m0 + m4];
        }
        {
            int k = tid >> 5, n4 = (tid & 31) * 4;
            *(float4*)&Bs[k][n4] = *(const float4*)&B[(size_t)(k0 + k) * ldb + n0 + n4];
        }
        __syncthreads();
#pragma unroll
        for (int k = 0; k < BK; k++) {
            float4 a0 = *(const float4*)&As[k][ty * 8];
            float4 a1 = *(const float4*)&As[k][ty * 8 + 4];
            float4 b0 = *(const float4*)&Bs[k][tx * 8];
            float4 b1 = *(const float4*)&Bs[k][tx * 8 + 4];
            float ar[8] = {a0.x, a0.y, a0.z, a0.w, a1.x, a1.y, a1.z, a1.w};
            float br[8] = {b0.x, b0.y, b0.z, b0.w, b1.x, b1.y, b1.z, b1.w};
#pragma unroll
            for (int i = 0; i < 8; i++)
#pragma unroll
                for (int j = 0; j < 8; j++) acc[i][j] += ar[i] * br[j];
        }
        __syncthreads();
    }
#pragma unroll
    for (int i = 0; i < 8; i++) {
        int m = m0 + ty * 8 + i;
        float4* cptr = (float4*)&C[(size_t)m * ldc + n0 + tx * 8];
        cptr[0] = make_float4(acc[i][0], acc[i][1], acc[i][2], acc[i][3]);
        cptr[1] = make_float4(acc[i][4], acc[i][5], acc[i][6], acc[i][7]);
    }
}

// ---------------- fp32 -> fp16 convert ----------------------------------------
__global__ void cvt_kernel(const float* __restrict__ x, __half* __restrict__ h, int n4) {
    int i = blockIdx.x * 256 + threadIdx.x;
    if (i >= n4) return;
    float4 v = ((const float4*)x)[i];
    __half2* H = (__half2*)h;
    H[2 * i]     = __floats2half2_rn(v.x, v.y);
    H[2 * i + 1] = __floats2half2_rn(v.z, v.w);
}

// ---------------- mma.sync fp16 GEMM, 128x128x32, double-buffered ------------
// D[m,n] = sum_k A[m,k]*B[n,k]; A,B K-major fp16. fp32 accumulate.
// SMEM rows padded to 80B: conflict-free ldmatrix.
#define STG_BYTES 20480   // A tile 128*80 + B tile 128*80

__device__ __forceinline__ void load_stage(uint32_t sb, const __half* pa,
                                           const __half* pb, int m0, int n0,
                                           int kk, int K, int r, int c) {
    const __half* ga = pa + (size_t)(m0 + r) * K + kk + c * 8;
    cp16(sb + r * 80 + c * 16, ga);
    cp16(sb + (r + 64) * 80 + c * 16, ga + (size_t)64 * K);
    const __half* gb = pb + (size_t)(n0 + r) * K + kk + c * 8;
    cp16(sb + 10240 + r * 80 + c * 16, gb);
    cp16(sb + 10240 + (r + 64) * 80 + c * 16, gb + (size_t)64 * K);
}

template <bool EPI>
__global__ __launch_bounds__(256, 1)
void mma_gemm(const __half* __restrict__ A, const __half* __restrict__ B,
              int K, long long sA, long long sB,
              __half* __restrict__ C, int ldc,
              float* __restrict__ E, const float* __restrict__ rq, const float* __restrict__ cv) {
    __shared__ __align__(128) uint8_t smbuf[2][STG_BYTES];
    const int tid = threadIdx.x, lid = tid & 31, wid = tid >> 5;
    const int wm = wid >> 2, wn = wid & 3;   // 2 x 4 warp grid
    const int m0 = blockIdx.y * 128, n0 = blockIdx.x * 128, bz = blockIdx.z;
    A += (size_t)bz * sA;
    B += (size_t)bz * sB;

    const int T = K / 32;
    const int lr = tid >> 2, lc = tid & 3;   // loader row/chunk

    float acc[4][4][4] = {};
    uint32_t sbase[2] = { smem_u32(smbuf[0]), smem_u32(smbuf[1]) };

    // prologue: stages 0,1
#pragma unroll
    for (int i = 0; i < 2; i++) {
        load_stage(sbase[i & 1], A, B, m0, n0, i * 32, K, lr, lc);
        cp_commit();
    }

    for (int i = 0; i < T; i++) {
        cp_wait1();
        __syncthreads();
        uint32_t sb = sbase[i & 1];

        uint32_t Af[2][4][4], Bf[2][2][4];
#pragma unroll
        for (int ks = 0; ks < 2; ks++) {
#pragma unroll
            for (int mf = 0; mf < 4; mf++) {
                int row = wm * 64 + mf * 16 + (lid & 15);
                int ch = ks * 2 + (lid >> 4);
                ldm4(sb + row * 80 + ch * 16,
                     Af[ks][mf][0], Af[ks][mf][1], Af[ks][mf][2], Af[ks][mf][3]);
            }
#pragma unroll
            for (int np = 0; np < 2; np++) {
                int g = lid >> 3;
                int row = wn * 32 + np * 16 + ((g >> 1) << 3) + (lid & 7);
                int ch = ks * 2 + (g & 1);
                ldm4(sb + 10240 + row * 80 + ch * 16,
                     Bf[ks][np][0], Bf[ks][np][1], Bf[ks][np][2], Bf[ks][np][3]);
            }
        }
        __syncthreads();
        if (i + 2 < T)
            load_stage(sbase[i & 1], A, B, m0, n0, (i + 2) * 32, K, lr, lc);
        cp_commit();
#pragma unroll
        for (int ks = 0; ks < 2; ks++)
#pragma unroll
            for (int mf = 0; mf < 4; mf++)
#pragma unroll
                for (int nf = 0; nf < 4; nf++) {
                    uint32_t b0 = Bf[ks][nf >> 1][(nf & 1) * 2];
                    uint32_t b1 = Bf[ks][nf >> 1][(nf & 1) * 2 + 1];
                    mma16816(acc[mf][nf][0], acc[mf][nf][1], acc[mf][nf][2], acc[mf][nf][3],
                             Af[ks][mf][0], Af[ks][mf][1], Af[ks][mf][2], Af[ks][mf][3],
                             b0, b1);
                }
    }

    // epilogue
    const int gr = lid >> 2, gc = (lid & 3) * 2;
#pragma unroll
    for (int mf = 0; mf < 4; mf++) {
        int m = m0 + wm * 64 + mf * 16 + gr;
        float r0v = 0.f, r1v = 0.f;
        if (EPI) { r0v = rq[bz * NQ + m]; r1v = rq[bz * NQ + m + 8]; }
#pragma unroll
        for (int nf = 0; nf < 4; nf++) {
            int n = n0 + wn * 32 + nf * 8 + gc;
            float c0 = acc[mf][nf][0], c1 = acc[mf][nf][1];
            float c2 = acc[mf][nf][2], c3 = acc[mf][nf][3];
            if (EPI) {
                float cv0 = cv[bz * NV + n], cv1 = cv[bz * NV + n + 1];
                size_t e0 = (size_t)bz * NQ * NV + (size_t)m * NV + n;
                float2 o0, o1;
                o0.x = __expf(tanhf(c0 + r0v + cv0));
                o0.y = __expf(tanhf(c1 + r0v + cv1));
                o1.x = __expf(tanhf(c2 + r1v + cv0));
                o1.y = __expf(tanhf(c3 + r1v + cv1));
                *(float2*)(E + e0) = o0;
                *(float2*)(E + e0 + (size_t)8 * NV) = o1;
            } else {
                size_t p0 = (size_t)m * ldc + n;
                size_t p1 = (size_t)(m + 8) * ldc + n;
                *(__half2*)(C + p0) = __floats2half2_rn(c0, c1);
                *(__half2*)(C + p1) = __floats2half2_rn(c2, c3);
            }
        }
    }
}

// ---------------- softmax reductions ----------------------------------------
__global__ void denomr_kernel() {
    int gw = (blockIdx.x * blockDim.x + threadIdx.x) >> 5;
    int lane = threadIdx.x & 31;
    const float* row = g_E + (size_t)gw * NV;
    float s = 0.f;
#pragma unroll 8
    for (int v = lane; v < NV; v += 32) s += row[v];
#pragma unroll
    for (int o = 16; o; o >>= 1) s += __shfl_xor_sync(0xffffffffu, s, o);
    if (!lane) g_invdr[gw] = 1.0f / s;
}

__global__ void denomc_kernel() {
    int b = blockIdx.y;
    int v = blockIdx.x * 256 + threadIdx.x;
    const float* Eb = g_E + (size_t)b * NQ * NV + v;
    float s = 0.f;
#pragma unroll 8
    for (int q = 0; q < NQ; q++) s += Eb[(size_t)q * NV];
    g_invdc[b * NV + v] = 1.0f / s;
}

__global__ void wq_kernel() {
    int gw = (blockIdx.x * blockDim.x + threadIdx.x) >> 5;
    int lane = threadIdx.x & 31;
    int b = gw >> 9;
    const float* row = g_E + (size_t)gw * NV;
    const float* dc = g_invdc + b * NV;
    float s = 0.f;
#pragma unroll 8
    for (int v = lane; v < NV; v += 32) s += row[v] * dc[v];
#pragma unroll
    for (int o = 16; o; o >>= 1) s += __shfl_xor_sync(0xffffffffu, s, o);
    if (!lane) g_wq[gw] = s;
}

__global__ void wv_kernel() {
    int b = blockIdx.y;
    int v = blockIdx.x * 256 + threadIdx.x;
    const float* Eb = g_E + (size_t)b * NQ * NV + v;
    const float* dr = g_invdr + b * NQ;
    float s = 0.f;
#pragma unroll 8
    for (int q = 0; q < NQ; q++) s += Eb[(size_t)q * NV] * dr[q];
    g_wv[b * NV + v] = s;
}

// ---------------- final pools -----------------------------------------------
__global__ void vhat_kernel(const float* __restrict__ V, float* __restrict__ out) {
    int b = blockIdx.x, d = threadIdx.x;
    const float* Vb = V + (size_t)b * NV * VD;
    const float* wv = g_wv + b * NV;
    float s = 0.f;
#pragma unroll 4
    for (int v = 0; v < NV; v++) s += wv[v] * Vb[(size_t)v * VD + d];
    out[b * VD + d] = s;
}

__global__ void qhat_kernel(const float* __restrict__ Q, float* __restrict__ out) {
    int b = blockIdx.x, d = threadIdx.x;
    const float* Qb = Q + (size_t)b * NQ * QD;
    const float* wq = g_wq + b * NQ;
    float s = 0.f;
#pragma unroll 4
    for (int q = 0; q < NQ; q++) s += wq[q] * Qb[(size_t)q * QD + d];
    out[B_ * VD + b * QD + d] = s;
}

// ---------------- launch -----------------------------------------------------
extern "C" void kernel_launch(void* const* d_in, const int* in_sizes, int n_in,
                              void* d_out, int out_size) {
    const float* V  = (const float*)d_in[0];
    const float* Q  = (const float*)d_in[1];
    const float* Wq = (const float*)d_in[2];
    const float* bq = (const float*)d_in[3];
    const float* Wv = (const float*)d_in[4];
    const float* bv = (const float*)d_in[5];
    float* out = (float*)d_out;

    float *pMT, *pa, *pc, *prq, *pcv, *pE;
    __half *pQf, *pVf, *pMTf, *pQMf;
    cudaGetSymbolAddress((void**)&pMT, g_MT);
    cudaGetSymbolAddress((void**)&pa, g_a);
    cudaGetSymbolAddress((void**)&pc, g_c);
    cudaGetSymbolAddress((void**)&prq, g_rq);
    cudaGetSymbolAddress((void**)&pcv, g_cv);
    cudaGetSymbolAddress((void**)&pE, g_E);
    cudaGetSymbolAddress((void**)&pQf, g_Qf);
    cudaGetSymbolAddress((void**)&pVf, g_Vf);
    cudaGetSymbolAddress((void**)&pMTf, g_MTf);
    cudaGetSymbolAddress((void**)&pQMf, g_QMf);

    // 1) a, c, s0
    compute_ac<<<6, 256>>>(Wq, Wv, bq, bv);
    // 2) MT[v,q] = sum_h Wv[h,v] * Wq[h,q]   (fp32, tiny)
    gemm_tn_kernel<<<dim3(QD / 128, VD / 128, 1), 256>>>(Wv, Wq, pMT, HIDD, VD, QD, QD);
    // 3) fp16 converts
    cvt_kernel<<<(VD * QD / 4 + 255) / 256, 256>>>(pMT, pMTf, VD * QD / 4);
    cvt_kernel<<<(B_ * NQ * QD / 4 + 255) / 256, 256>>>(Q, pQf, B_ * NQ * QD / 4);
    cvt_kernel<<<(B_ * NV * VD / 4 + 255) / 256, 256>>>(V, pVf, B_ * NV * VD / 4);
    // 4) rq = Q.a + s0 ; cv = V.c
    rowdot_kernel<true><<<(B_ * NQ) / 8, 256>>>(Q, pa, prq, QD);
    rowdot_kernel<false><<<(B_ * NV) / 8, 256>>>(V, pc, pcv, VD);
    // 5) QM = Q @ MT^T  (mma.sync fp16), epilogue writes QM fp16
    mma_gemm<false><<<dim3(VD / 128, (B_ * NQ) / 128, 1), 256>>>(
        pQf, pMTf, QD, 0, 0, pQMf, VD, nullptr, nullptr, nullptr);
    // 6) E = exp(tanh(QM @ V^T + rq + cv))  (mma.sync fp16, batched)
    mma_gemm<true><<<dim3(NV / 128, NQ / 128, B_), 256>>>(
        pQMf, pVf, VD, (long long)NQ * VD, (long long)NV * VD,
        nullptr, 0, pE, prq, pcv);
    // 7) softmax denominators, pooled softmax weights
    denomr_kernel<<<(B_ * NQ) / 8, 256>>>();
    denomc_kernel<<<dim3(NV / 256, B_), 256>>>();
    wq_kernel<<<(B_ * NQ) / 8, 256>>>();
    wv_kernel<<<dim3(NV / 256, B_), 256>>>();
    // 8) pools
    vhat_kernel<<<B_, VD>>>(V, out);
    qhat_kernel<<<B_, QD>>>(Q, out);
}

// round 6
// speedup vs baseline: 2.6778x; 1.1553x over previous
#include <cuda_runtime.h>
#include <cuda_fp16.h>
#include <cstdint>

#define B_   64
#define NQ   512
#define NV   1024
#define QD   768
#define VD   512
#define HIDD 512

// ---------------- scratch (device globals; no allocation allowed) ----------
__device__ float g_MT[VD * QD];                // MT[v,q] = sum_h Wv[h,v] Wq[h,q]
__device__ float g_a[QD];
__device__ float g_c[VD];
__device__ float g_s0;
__device__ float g_rq[B_ * NQ];
__device__ float g_cv[B_ * NV];
__device__ __align__(16) __half g_Qf[(size_t)B_ * NQ * QD];
__device__ __align__(16) __half g_Vf[(size_t)B_ * NV * VD];
__device__ __align__(16) __half g_MTf[VD * QD];
__device__ __align__(16) __half g_QMf[(size_t)B_ * NQ * VD];
__device__ __align__(16) __half g_E[(size_t)B_ * NQ * NV];
__device__ float g_invdr[B_ * NQ];
__device__ float g_invdc[B_ * NV];
__device__ float g_wq[B_ * NQ];
__device__ float g_wv[B_ * NV];

// ---------------- PTX helpers (sm_80+ features only) ------------------------
__device__ __forceinline__ uint32_t smem_u32(const void* p) {
    uint32_t a;
    asm("{ .reg .u64 t; cvta.to.shared.u64 t, %1; cvt.u32.u64 %0, t; }" : "=r"(a) : "l"(p));
    return a;
}
__device__ __forceinline__ void cp16(uint32_t s, const void* g) {
    asm volatile("cp.async.cg.shared.global [%0], [%1], 16;" :: "r"(s), "l"(g));
}
__device__ __forceinline__ void cp_commit() { asm volatile("cp.async.commit_group;" ::: "memory"); }
__device__ __forceinline__ void cp_wait1()  { asm volatile("cp.async.wait_group 1;" ::: "memory"); }

__device__ __forceinline__ void ldm4(uint32_t a, uint32_t& r0, uint32_t& r1,
                                     uint32_t& r2, uint32_t& r3) {
    asm volatile("ldmatrix.sync.aligned.m8n8.x4.shared.b16 {%0,%1,%2,%3}, [%4];"
                 : "=r"(r0), "=r"(r1), "=r"(r2), "=r"(r3) : "r"(a));
}
__device__ __forceinline__ void mma16816(float& c0, float& c1, float& c2, float& c3,
                                         uint32_t a0, uint32_t a1, uint32_t a2, uint32_t a3,
                                         uint32_t b0, uint32_t b1) {
    asm volatile("mma.sync.aligned.m16n8k16.row.col.f32.f16.f16.f32 "
                 "{%0,%1,%2,%3}, {%4,%5,%6,%7}, {%8,%9}, {%0,%1,%2,%3};"
                 : "+f"(c0), "+f"(c1), "+f"(c2), "+f"(c3)
                 : "r"(a0), "r"(a1), "r"(a2), "r"(a3), "r"(b0), "r"(b1));
}

// ---------------- small precompute: a, c, s0 -------------------------------
__global__ void compute_ac(const float* __restrict__ Wq, const float* __restrict__ Wv,
                           const float* __restrict__ bq, const float* __restrict__ bv) {
    int t = blockIdx.x * 256 + threadIdx.x;
    if (t < QD) {
        float s = 0.f;
        for (int h = 0; h < HIDD; h++) s += Wq[h * QD + t] * bv[h];
        g_a[t] = s;
    } else if (t < QD + VD) {
        int e = t - QD;
        float s = 0.f;
        for (int h = 0; h < HIDD; h++) s += Wv[h * VD + e] * bq[h];
        g_c[e] = s;
    } else if (t == QD + VD) {
        float s = 0.f;
        for (int h = 0; h < HIDD; h++) s += bq[h] * bv[h];
        g_s0 = s;
    }
}

// ---------------- fused fp32->fp16 convert + row-dot -------------------------
// One warp per row: writes fp16 row and out[row] = X[row,:].vec (+ s0).
// NF4 = K/4/32 float4-chunks per lane.
template <int K, int NF4, bool ADD_S0>
__global__ void fuse_cvt_dot(const float* __restrict__ X, __half* __restrict__ Xf,
                             const float* __restrict__ vec, float* __restrict__ out) {
    int row = blockIdx.x * 8 + (threadIdx.x >> 5);
    int lane = threadIdx.x & 31;
    const float4* xr = (const float4*)(X + (size_t)row * K);
    const float4* vr = (const float4*)vec;
    __half2* hr = (__half2*)(Xf + (size_t)row * K);
    float s = 0.f;
#pragma unroll
    for (int j = 0; j < NF4; j++) {
        int idx = lane + j * 32;
        float4 v = xr[idx];
        float4 a = vr[idx];
        s += v.x * a.x + v.y * a.y + v.z * a.z + v.w * a.w;
        hr[2 * idx]     = __floats2half2_rn(v.x, v.y);
        hr[2 * idx + 1] = __floats2half2_rn(v.z, v.w);
    }
#pragma unroll
    for (int o = 16; o; o >>= 1) s += __shfl_xor_sync(0xffffffffu, s, o);
    if (!lane) out[row] = s + (ADD_S0 ? g_s0 : 0.f);
}

// ---------------- fp32 GEMM (only for tiny MT = Wv^T Wq) --------------------
__global__ __launch_bounds__(256)
void gemm_tn_kernel(const float* __restrict__ A, const float* __restrict__ B,
                    float* __restrict__ C, int K, int lda, int ldb, int ldc) {
    const int BM = 128, BN = 128, BK = 8;
    const int m0 = blockIdx.y * BM, n0 = blockIdx.x * BN;
    __shared__ float As[BK][BM + 4];
    __shared__ float Bs[BK][BN + 4];
    const int tid = threadIdx.x;
    const int tx = tid & 15, ty = tid >> 4;
    float acc[8][8];
#pragma unroll
    for (int i = 0; i < 8; i++)
#pragma unroll
        for (int j = 0; j < 8; j++) acc[i][j] = 0.f;
    for (int k0 = 0; k0 < K; k0 += BK) {
        {
            int k = tid >> 5, m4 = (tid & 31) * 4;
            *(float4*)&As[k][m4] = *(const float4*)&A[(size_t)(k0 + k) * lda + m0 + m4];
        }
        {
            int k = tid >> 5, n4 = (tid & 31) * 4;
            *(float4*)&Bs[k][n4] = *(const float4*)&B[(size_t)(k0 + k) * ldb + n0 + n4];
        }
        __syncthreads();
#pragma unroll
        for (int k = 0; k < BK; k++) {
            float4 a0 = *(const float4*)&As[k][ty * 8];
            float4 a1 = *(const float4*)&As[k][ty * 8 + 4];
            float4 b0 = *(const float4*)&Bs[k][tx * 8];
            float4 b1 = *(const float4*)&Bs[k][tx * 8 + 4];
            float ar[8] = {a0.x, a0.y, a0.z, a0.w, a1.x, a1.y, a1.z, a1.w};
            float br[8] = {b0.x, b0.y, b0.z, b0.w, b1.x, b1.y, b1.z, b1.w};
#pragma unroll
            for (int i = 0; i < 8; i++)
#pragma unroll
                for (int j = 0; j < 8; j++) acc[i][j] += ar[i] * br[j];
        }
        __syncthreads();
    }
#pragma unroll
    for (int i = 0; i < 8; i++) {
        int m = m0 + ty * 8 + i;
        float4* cptr = (float4*)&C[(size_t)m * ldc + n0 + tx * 8];
        cptr[0] = make_float4(acc[i][0], acc[i][1], acc[i][2], acc[i][3]);
        cptr[1] = make_float4(acc[i][4], acc[i][5], acc[i][6], acc[i][7]);
    }
}

// ---------------- fp32 -> fp16 convert (tiny MT only) -------------------------
__global__ void cvt_kernel(const float* __restrict__ x, __half* __restrict__ h, int n4) {
    int i = blockIdx.x * 256 + threadIdx.x;
    if (i >= n4) return;
    float4 v = ((const float4*)x)[i];
    __half2* H = (__half2*)h;
    H[2 * i]     = __floats2half2_rn(v.x, v.y);
    H[2 * i + 1] = __floats2half2_rn(v.z, v.w);
}

// ---------------- mma.sync fp16 GEMM, 128x128x32, double-buffered ------------
#define STG_BYTES 20480   // A tile 128*80 + B tile 128*80

__device__ __forceinline__ void load_stage(uint32_t sb, const __half* pa,
                                           const __half* pb, int m0, int n0,
                                           int kk, int K, int r, int c) {
    const __half* ga = pa + (size_t)(m0 + r) * K + kk + c * 8;
    cp16(sb + r * 80 + c * 16, ga);
    cp16(sb + (r + 64) * 80 + c * 16, ga + (size_t)64 * K);
    const __half* gb = pb + (size_t)(n0 + r) * K + kk + c * 8;
    cp16(sb + 10240 + r * 80 + c * 16, gb);
    cp16(sb + 10240 + (r + 64) * 80 + c * 16, gb + (size_t)64 * K);
}

template <bool EPI>
__global__ __launch_bounds__(256, 1)
void mma_gemm(const __half* __restrict__ A, const __half* __restrict__ B,
              int K, long long sA, long long sB,
              __half* __restrict__ C, int ldc,
              __half* __restrict__ E, const float* __restrict__ rq, const float* __restrict__ cv) {
    __shared__ __align__(128) uint8_t smbuf[2][STG_BYTES];
    const int tid = threadIdx.x, lid = tid & 31, wid = tid >> 5;
    const int wm = wid >> 2, wn = wid & 3;   // 2 x 4 warp grid
    const int m0 = blockIdx.y * 128, n0 = blockIdx.x * 128, bz = blockIdx.z;
    A += (size_t)bz * sA;
    B += (size_t)bz * sB;

    const int T = K / 32;
    const int lr = tid >> 2, lc = tid & 3;   // loader row/chunk

    float acc[4][4][4] = {};
    uint32_t sbase[2] = { smem_u32(smbuf[0]), smem_u32(smbuf[1]) };

#pragma unroll
    for (int i = 0; i < 2; i++) {
        load_stage(sbase[i & 1], A, B, m0, n0, i * 32, K, lr, lc);
        cp_commit();
    }

    for (int i = 0; i < T; i++) {
        cp_wait1();
        __syncthreads();
        uint32_t sb = sbase[i & 1];

        uint32_t Af[2][4][4], Bf[2][2][4];
#pragma unroll
        for (int ks = 0; ks < 2; ks++) {
#pragma unroll
            for (int mf = 0; mf < 4; mf++) {
                int row = wm * 64 + mf * 16 + (lid & 15);
                int ch = ks * 2 + (lid >> 4);
                ldm4(sb + row * 80 + ch * 16,
                     Af[ks][mf][0], Af[ks][mf][1], Af[ks][mf][2], Af[ks][mf][3]);
            }
#pragma unroll
            for (int np = 0; np < 2; np++) {
                int g = lid >> 3;
                int row = wn * 32 + np * 16 + ((g >> 1) << 3) + (lid & 7);
                int ch = ks * 2 + (g & 1);
                ldm4(sb + 10240 + row * 80 + ch * 16,
                     Bf[ks][np][0], Bf[ks][np][1], Bf[ks][np][2], Bf[ks][np][3]);
            }
        }
        __syncthreads();
        if (i + 2 < T)
            load_stage(sbase[i & 1], A, B, m0, n0, (i + 2) * 32, K, lr, lc);
        cp_commit();
#pragma unroll
        for (int ks = 0; ks < 2; ks++)
#pragma unroll
            for (int mf = 0; mf < 4; mf++)
#pragma unroll
                for (int nf = 0; nf < 4; nf++) {
                    uint32_t b0 = Bf[ks][nf >> 1][(nf & 1) * 2];
                    uint32_t b1 = Bf[ks][nf >> 1][(nf & 1) * 2 + 1];
                    mma16816(acc[mf][nf][0], acc[mf][nf][1], acc[mf][nf][2], acc[mf][nf][3],
                             Af[ks][mf][0], Af[ks][mf][1], Af[ks][mf][2], Af[ks][mf][3],
                             b0, b1);
                }
    }

    // epilogue
    const int gr = lid >> 2, gc = (lid & 3) * 2;
#pragma unroll
    for (int mf = 0; mf < 4; mf++) {
        int m = m0 + wm * 64 + mf * 16 + gr;
        float r0v = 0.f, r1v = 0.f;
        if (EPI) { r0v = rq[bz * NQ + m]; r1v = rq[bz * NQ + m + 8]; }
#pragma unroll
        for (int nf = 0; nf < 4; nf++) {
            int n = n0 + wn * 32 + nf * 8 + gc;
            float c0 = acc[mf][nf][0], c1 = acc[mf][nf][1];
            float c2 = acc[mf][nf][2], c3 = acc[mf][nf][3];
            if (EPI) {
                float cv0 = cv[bz * NV + n], cv1 = cv[bz * NV + n + 1];
                size_t e0 = (size_t)bz * NQ * NV + (size_t)m * NV + n;
                *(__half2*)(E + e0) = __floats2half2_rn(
                    __expf(tanhf(c0 + r0v + cv0)), __expf(tanhf(c1 + r0v + cv1)));
                *(__half2*)(E + e0 + (size_t)8 * NV) = __floats2half2_rn(
                    __expf(tanhf(c2 + r1v + cv0)), __expf(tanhf(c3 + r1v + cv1)));
            } else {
                size_t p0 = (size_t)m * ldc + n;
                size_t p1 = (size_t)(m + 8) * ldc + n;
                *(__half2*)(C + p0) = __floats2half2_rn(c0, c1);
                *(__half2*)(C + p1) = __floats2half2_rn(c2, c3);
            }
        }
    }
}

// ---------------- softmax reductions (fp16 E) --------------------------------
__global__ void denomr_kernel() {  // invdr[r] = 1 / sum_v E[r,v]
    int gw = (blockIdx.x * blockDim.x + threadIdx.x) >> 5;
    int lane = threadIdx.x & 31;
    const __half2* row = (const __half2*)(g_E + (size_t)gw * NV);
    float s = 0.f;
#pragma unroll
    for (int j = 0; j < NV / 64; j++) {
        float2 v = __half22float2(row[lane + j * 32]);
        s += v.x + v.y;
    }
#pragma unroll
    for (int o = 16; o; o >>= 1) s += __shfl_xor_sync(0xffffffffu, s, o);
    if (!lane) g_invdr[gw] = 1.0f / s;
}

__global__ void denomc_kernel() {  // invdc[b,v] = 1 / sum_q E[b,q,v]  (2 cols/thread)
    int b = blockIdx.y;
    int v2 = blockIdx.x * 256 + threadIdx.x;
    const __half2* Eb = (const __half2*)(g_E + (size_t)b * NQ * NV) + v2;
    float s0 = 0.f, s1 = 0.f;
#pragma unroll 8
    for (int q = 0; q < NQ; q++) {
        float2 v = __half22float2(Eb[(size_t)q * (NV / 2)]);
        s0 += v.x; s1 += v.y;
    }
    g_invdc[b * NV + 2 * v2]     = 1.0f / s0;
    g_invdc[b * NV + 2 * v2 + 1] = 1.0f / s1;
}

__global__ void wq_kernel() {  // wq[b,q] = sum_v E[b,q,v] * invdc[b,v]
    int gw = (blockIdx.x * blockDim.x + threadIdx.x) >> 5;
    int lane = threadIdx.x & 31;
    int b = gw >> 9;
    const __half2* row = (const __half2*)(g_E + (size_t)gw * NV);
    const float2* dc = (const float2*)(g_invdc + b * NV);
    float s = 0.f;
#pragma unroll
    for (int j = 0; j < NV / 64; j++) {
        int idx = lane + j * 32;
        float2 v = __half22float2(row[idx]);
        float2 d = dc[idx];
        s += v.x * d.x + v.y * d.y;
    }
#pragma unroll
    for (int o = 16; o; o >>= 1) s += __shfl_xor_sync(0xffffffffu, s, o);
    if (!lane) g_wq[gw] = s;
}

__global__ void wv_kernel() {  // wv[b,v] = sum_q E[b,q,v] * invdr[b,q]  (2 cols/thread)
    int b = blockIdx.y;
    int v2 = blockIdx.x * 256 + threadIdx.x;
    const __half2* Eb = (const __half2*)(g_E + (size_t)b * NQ * NV) + v2;
    const float* dr = g_invdr + b * NQ;
    float s0 = 0.f, s1 = 0.f;
#pragma unroll 8
    for (int q = 0; q < NQ; q++) {
        float2 v = __half22float2(Eb[(size_t)q * (NV / 2)]);
        float d = dr[q];
        s0 += v.x * d; s1 += v.y * d;
    }
    g_wv[b * NV + 2 * v2]     = s0;
    g_wv[b * NV + 2 * v2 + 1] = s1;
}

// ---------------- final pools (read fp16 Q/V) ---------------------------------
__global__ void vhat_kernel(float* __restrict__ out) {
    int b = blockIdx.x, d = threadIdx.x;
    const __half* Vb = g_Vf + (size_t)b * NV * VD;
    const float* wv = g_wv + b * NV;
    float s = 0.f;
#pragma unroll 4
    for (int v = 0; v < NV; v++) s += wv[v] * __half2float(Vb[(size_t)v * VD + d]);
    out[b * VD + d] = s;
}

__global__ void qhat_kernel(float* __restrict__ out) {
    int b = blockIdx.x, d = threadIdx.x;
    const __half* Qb = g_Qf + (size_t)b * NQ * QD;
    const float* wq = g_wq + b * NQ;
    float s = 0.f;
#pragma unroll 4
    for (int q = 0; q < NQ; q++) s += wq[q] * __half2float(Qb[(size_t)q * QD + d]);
    out[B_ * VD + b * QD + d] = s;
}

// ---------------- launch -----------------------------------------------------
extern "C" void kernel_launch(void* const* d_in, const int* in_sizes, int n_in,
                              void* d_out, int out_size) {
    const float* V  = (const float*)d_in[0];
    const float* Q  = (const float*)d_in[1];
    const float* Wq = (const float*)d_in[2];
    const float* bq = (const float*)d_in[3];
    const float* Wv = (const float*)d_in[4];
    const float* bv = (const float*)d_in[5];
    float* out = (float*)d_out;

    float *pMT, *pa, *pc, *prq, *pcv;
    __half *pQf, *pVf, *pMTf, *pQMf, *pE;
    cudaGetSymbolAddress((void**)&pMT, g_MT);
    cudaGetSymbolAddress((void**)&pa, g_a);
    cudaGetSymbolAddress((void**)&pc, g_c);
    cudaGetSymbolAddress((void**)&prq, g_rq);
    cudaGetSymbolAddress((void**)&pcv, g_cv);
    cudaGetSymbolAddress((void**)&pE, g_E);
    cudaGetSymbolAddress((void**)&pQf, g_Qf);
    cudaGetSymbolAddress((void**)&pVf, g_Vf);
    cudaGetSymbolAddress((void**)&pMTf, g_MTf);
    cudaGetSymbolAddress((void**)&pQMf, g_QMf);

    // 1) a, c, s0
    compute_ac<<<6, 256>>>(Wq, Wv, bq, bv);
    // 2) MT[v,q] = sum_h Wv[h,v] * Wq[h,q]   (fp32, tiny)
    gemm_tn_kernel<<<dim3(QD / 128, VD / 128, 1), 256>>>(Wv, Wq, pMT, HIDD, VD, QD, QD);
    cvt_kernel<<<(VD * QD / 4 + 255) / 256, 256>>>(pMT, pMTf, VD * QD / 4);
    // 3) fused convert + row-dot (single read of Q and V)
    fuse_cvt_dot<QD, QD / 128, true><<<(B_ * NQ) / 8, 256>>>(Q, pQf, pa, prq);
    fuse_cvt_dot<VD, VD / 128, false><<<(B_ * NV) / 8, 256>>>(V, pVf, pc, pcv);
    // 4) QM = Q @ MT^T  (mma.sync fp16)
    mma_gemm<false><<<dim3(VD / 128, (B_ * NQ) / 128, 1), 256>>>(
        pQf, pMTf, QD, 0, 0, pQMf, VD, nullptr, nullptr, nullptr);
    // 5) E = exp(tanh(QM @ V^T + rq + cv))  -> fp16
    mma_gemm<true><<<dim3(NV / 128, NQ / 128, B_), 256>>>(
        pQMf, pVf, VD, (long long)NQ * VD, (long long)NV * VD,
        nullptr, 0, pE, prq, pcv);
    // 6) softmax denominators, pooled softmax weights (fp16 E reads)
    denomr_kernel<<<(B_ * NQ) / 8, 256>>>();
    denomc_kernel<<<dim3(NV / 512, B_), 256>>>();
    wq_kernel<<<(B_ * NQ) / 8, 256>>>();
    wv_kernel<<<dim3(NV / 512, B_), 256>>>();
    // 7) pools (fp16 Q/V reads)
    vhat_kernel<<<B_, VD>>>(out);
    qhat_kernel<<<B_, QD>>>(out);
}

// round 7
// speedup vs baseline: 2.7591x; 1.0304x over previous
#include <cuda_runtime.h>
#include <cuda_fp16.h>
#include <cstdint>

#define B_   64
#define NQ   512
#define NV   1024
#define QD   768
#define VD   512
#define HIDD 512

// ---------------- scratch (device globals; no allocation allowed) ----------
__device__ __align__(16) float g_a[QD];
__device__ __align__(16) float g_c[VD];
__device__ float g_s0;
__device__ float g_rq[B_ * NQ];
__device__ float g_cv[B_ * NV];
__device__ __align__(16) __half g_Qf[(size_t)B_ * NQ * QD];
__device__ __align__(16) __half g_Vf[(size_t)B_ * NV * VD];
__device__ __align__(16) __half g_MTf[VD * QD];
__device__ __align__(16) __half g_QMf[(size_t)B_ * NQ * VD];
__device__ __align__(16) __half g_E[(size_t)B_ * NQ * NV];
// atomic accumulators (zeroed each call by compute_ac): [dr | dc | wv]
#define ZN (B_ * NQ + 2 * B_ * NV)
__device__ float g_zero[ZN];
__device__ float g_wq[B_ * NQ];

// ---------------- PTX helpers (sm_80+ features only) ------------------------
__device__ __forceinline__ uint32_t smem_u32(const void* p) {
    uint32_t a;
    asm("{ .reg .u64 t; cvta.to.shared.u64 t, %1; cvt.u32.u64 %0, t; }" : "=r"(a) : "l"(p));
    return a;
}
__device__ __forceinline__ void cp16(uint32_t s, const void* g) {
    asm volatile("cp.async.cg.shared.global [%0], [%1], 16;" :: "r"(s), "l"(g));
}
__device__ __forceinline__ void cp_commit() { asm volatile("cp.async.commit_group;" ::: "memory"); }
__device__ __forceinline__ void cp_wait1()  { asm volatile("cp.async.wait_group 1;" ::: "memory"); }

__device__ __forceinline__ void ldm4(uint32_t a, uint32_t& r0, uint32_t& r1,
                                     uint32_t& r2, uint32_t& r3) {
    asm volatile("ldmatrix.sync.aligned.m8n8.x4.shared.b16 {%0,%1,%2,%3}, [%4];"
                 : "=r"(r0), "=r"(r1), "=r"(r2), "=r"(r3) : "r"(a));
}
__device__ __forceinline__ void mma16816(float& c0, float& c1, float& c2, float& c3,
                                         uint32_t a0, uint32_t a1, uint32_t a2, uint32_t a3,
                                         uint32_t b0, uint32_t b1) {
    asm volatile("mma.sync.aligned.m16n8k16.row.col.f32.f16.f16.f32 "
                 "{%0,%1,%2,%3}, {%4,%5,%6,%7}, {%8,%9}, {%0,%1,%2,%3};"
                 : "+f"(c0), "+f"(c1), "+f"(c2), "+f"(c3)
                 : "r"(a0), "r"(a1), "r"(a2), "r"(a3), "r"(b0), "r"(b1));
}

// ---------------- precompute a, c, s0 + zero the atomic accumulators --------
__global__ void compute_ac(const float* __restrict__ Wq, const float* __restrict__ Wv,
                           const float* __restrict__ bq, const float* __restrict__ bv) {
    int t = blockIdx.x * 1024 + threadIdx.x;
    if (t < ZN) g_zero[t] = 0.f;
    if (t < QD) {
        float s = 0.f;
        for (int h = 0; h < HIDD; h++) s += Wq[h * QD + t] * bv[h];
        g_a[t] = s;
    } else if (t < QD + VD) {
        int e = t - QD;
        float s = 0.f;
        for (int h = 0; h < HIDD; h++) s += Wv[h * VD + e] * bq[h];
        g_c[e] = s;
    } else if (t == QD + VD) {
        float s = 0.f;
        for (int h = 0; h < HIDD; h++) s += bq[h] * bv[h];
        g_s0 = s;
    }
}

// ---------------- fused fp32->fp16 convert + row-dot -------------------------
template <int K, int NF4, bool ADD_S0>
__global__ void fuse_cvt_dot(const float* __restrict__ X, __half* __restrict__ Xf,
                             const float* __restrict__ vec, float* __restrict__ out) {
    int row = blockIdx.x * 8 + (threadIdx.x >> 5);
    int lane = threadIdx.x & 31;
    const float4* xr = (const float4*)(X + (size_t)row * K);
    const float4* vr = (const float4*)vec;
    __half2* hr = (__half2*)(Xf + (size_t)row * K);
    float s = 0.f;
#pragma unroll
    for (int j = 0; j < NF4; j++) {
        int idx = lane + j * 32;
        float4 v = xr[idx];
        float4 a = vr[idx];
        s += v.x * a.x + v.y * a.y + v.z * a.z + v.w * a.w;
        hr[2 * idx]     = __floats2half2_rn(v.x, v.y);
        hr[2 * idx + 1] = __floats2half2_rn(v.z, v.w);
    }
#pragma unroll
    for (int o = 16; o; o >>= 1) s += __shfl_xor_sync(0xffffffffu, s, o);
    if (!lane) out[row] = s + (ADD_S0 ? g_s0 : 0.f);
}

// ---------------- fp32 GEMM -> fp16 out (tiny MT = Wv^T Wq) ------------------
__global__ __launch_bounds__(256)
void gemm_tn_kernel(const float* __restrict__ A, const float* __restrict__ B,
                    __half* __restrict__ C, int K, int lda, int ldb, int ldc) {
    const int BM = 128, BN = 128, BK = 8;
    const int m0 = blockIdx.y * BM, n0 = blockIdx.x * BN;
    __shared__ float As[BK][BM + 4];
    __shared__ float Bs[BK][BN + 4];
    const int tid = threadIdx.x;
    const int tx = tid & 15, ty = tid >> 4;
    float acc[8][8];
#pragma unroll
    for (int i = 0; i < 8; i++)
#pragma unroll
        for (int j = 0; j < 8; j++) acc[i][j] = 0.f;
    for (int k0 = 0; k0 < K; k0 += BK) {
        {
            int k = tid >> 5, m4 = (tid & 31) * 4;
            *(float4*)&As[k][m4] = *(const float4*)&A[(size_t)(k0 + k) * lda + m0 + m4];
        }
        {
            int k = tid >> 5, n4 = (tid & 31) * 4;
            *(float4*)&Bs[k][n4] = *(const float4*)&B[(size_t)(k0 + k) * ldb + n0 + n4];
        }
        __syncthreads();
#pragma unroll
        for (int k = 0; k < BK; k++) {
            float4 a0 = *(const float4*)&As[k][ty * 8];
            float4 a1 = *(const float4*)&As[k][ty * 8 + 4];
            float4 b0 = *(const float4*)&Bs[k][tx * 8];
            float4 b1 = *(const float4*)&Bs[k][tx * 8 + 4];
            float ar[8] = {a0.x, a0.y, a0.z, a0.w, a1.x, a1.y, a1.z, a1.w};
            float br[8] = {b0.x, b0.y, b0.z, b0.w, b1.x, b1.y, b1.z, b1.w};
#pragma unroll
            for (int i = 0; i < 8; i++)
#pragma unroll
                for (int j = 0; j < 8; j++) acc[i][j] += ar[i] * br[j];
        }
        __syncthreads();
    }
#pragma unroll
    for (int i = 0; i < 8; i++) {
        int m = m0 + ty * 8 + i;
        __half2* cptr = (__half2*)&C[(size_t)m * ldc + n0 + tx * 8];
#pragma unroll
        for (int j = 0; j < 4; j++)
            cptr[j] = __floats2half2_rn(acc[i][2 * j], acc[i][2 * j + 1]);
    }
}

// ---------------- mma.sync fp16 GEMM, 128x128x32, 3-stage pipeline ----------
#define STG_BYTES 20480   // A tile 128*80 + B tile 128*80
#define SMEM_DYN  (3 * STG_BYTES)

__device__ __forceinline__ void load_stage(uint32_t sb, const __half* pa,
                                           const __half* pb, int m0, int n0,
                                           int kk, int K, int r, int c) {
    const __half* ga = pa + (size_t)(m0 + r) * K + kk + c * 8;
    cp16(sb + r * 80 + c * 16, ga);
    cp16(sb + (r + 64) * 80 + c * 16, ga + (size_t)64 * K);
    const __half* gb = pb + (size_t)(n0 + r) * K + kk + c * 8;
    cp16(sb + 10240 + r * 80 + c * 16, gb);
    cp16(sb + 10240 + (r + 64) * 80 + c * 16, gb + (size_t)64 * K);
}

// EPI=false: C = fp16(acc).  EPI=true: E=fp16(exp(tanh(acc+rq+cv))) + atomic row/col sums.
template <bool EPI>
__global__ __launch_bounds__(256, 1)
void mma_gemm(const __half* __restrict__ A, const __half* __restrict__ B,
              int K, long long sA, long long sB,
              __half* __restrict__ C, int ldc,
              __half* __restrict__ E, const float* __restrict__ rq, const float* __restrict__ cv,
              float* __restrict__ dr, float* __restrict__ dc) {
    extern __shared__ __align__(128) uint8_t smbuf[];
    const int tid = threadIdx.x, lid = tid & 31, wid = tid >> 5;
    const int wm = wid >> 2, wn = wid & 3;   // 2 x 4 warp grid
    const int m0 = blockIdx.y * 128, n0 = blockIdx.x * 128, bz = blockIdx.z;
    A += (size_t)bz * sA;
    B += (size_t)bz * sB;

    const int T = K / 32;
    const int lr = tid >> 2, lc = tid & 3;   // loader row/chunk

    float acc[4][4][4] = {};
    uint32_t sb0 = smem_u32(smbuf);

#pragma unroll
    for (int i = 0; i < 2; i++) {
        load_stage(sb0 + i * STG_BYTES, A, B, m0, n0, i * 32, K, lr, lc);
        cp_commit();
    }

    for (int i = 0; i < T; i++) {
        cp_wait1();
        __syncthreads();
        if (i + 2 < T) {
            int s = (i + 2) % 3;
            load_stage(sb0 + s * STG_BYTES, A, B, m0, n0, (i + 2) * 32, K, lr, lc);
        }
        cp_commit();
        uint32_t sb = sb0 + (i % 3) * STG_BYTES;

        uint32_t Af[2][4][4], Bf[2][2][4];
#pragma unroll
        for (int ks = 0; ks < 2; ks++) {
#pragma unroll
            for (int mf = 0; mf < 4; mf++) {
                int row = wm * 64 + mf * 16 + (lid & 15);
                int ch = ks * 2 + (lid >> 4);
                ldm4(sb + row * 80 + ch * 16,
                     Af[ks][mf][0], Af[ks][mf][1], Af[ks][mf][2], Af[ks][mf][3]);
            }
#pragma unroll
            for (int np = 0; np < 2; np++) {
                int g = lid >> 3;
                int row = wn * 32 + np * 16 + ((g >> 1) << 3) + (lid & 7);
                int ch = ks * 2 + (g & 1);
                ldm4(sb + 10240 + row * 80 + ch * 16,
                     Bf[ks][np][0], Bf[ks][np][1], Bf[ks][np][2], Bf[ks][np][3]);
            }
        }
#pragma unroll
        for (int ks = 0; ks < 2; ks++)
#pragma unroll
            for (int mf = 0; mf < 4; mf++)
#pragma unroll
                for (int nf = 0; nf < 4; nf++) {
                    uint32_t b0 = Bf[ks][nf >> 1][(nf & 1) * 2];
                    uint32_t b1 = Bf[ks][nf >> 1][(nf & 1) * 2 + 1];
                    mma16816(acc[mf][nf][0], acc[mf][nf][1], acc[mf][nf][2], acc[mf][nf][3],
                             Af[ks][mf][0], Af[ks][mf][1], Af[ks][mf][2], Af[ks][mf][3],
                             b0, b1);
                }
    }

    // epilogue
    const int gr = lid >> 2, gc = (lid & 3) * 2;
    if (!EPI) {
#pragma unroll
        for (int mf = 0; mf < 4; mf++) {
            int m = m0 + wm * 64 + mf * 16 + gr;
#pragma unroll
            for (int nf = 0; nf < 4; nf++) {
                int n = n0 + wn * 32 + nf * 8 + gc;
                *(__half2*)(C + (size_t)m * ldc + n) =
                    __floats2half2_rn(acc[mf][nf][0], acc[mf][nf][1]);
                *(__half2*)(C + (size_t)(m + 8) * ldc + n) =
                    __floats2half2_rn(acc[mf][nf][2], acc[mf][nf][3]);
            }
        }
    } else {
        float colp[4][2] = {};
        float rowp0[4], rowp1[4];
#pragma unroll
        for (int mf = 0; mf < 4; mf++) {
            int m = m0 + wm * 64 + mf * 16 + gr;
            float r0v = rq[bz * NQ + m], r1v = rq[bz * NQ + m + 8];
            float s0 = 0.f, s1 = 0.f;
#pragma unroll
            for (int nf = 0; nf < 4; nf++) {
                int n = n0 + wn * 32 + nf * 8 + gc;
                float cv0 = cv[bz * NV + n], cv1 = cv[bz * NV + n + 1];
                float e00 = __expf(tanhf(acc[mf][nf][0] + r0v + cv0));
                float e01 = __expf(tanhf(acc[mf][nf][1] + r0v + cv1));
                float e10 = __expf(tanhf(acc[mf][nf][2] + r1v + cv0));
                float e11 = __expf(tanhf(acc[mf][nf][3] + r1v + cv1));
                size_t e0 = (size_t)bz * NQ * NV + (size_t)m * NV + n;
                *(__half2*)(E + e0) = __floats2half2_rn(e00, e01);
                *(__half2*)(E + e0 + (size_t)8 * NV) = __floats2half2_rn(e10, e11);
                s0 += e00 + e01;
                s1 += e10 + e11;
                colp[nf][0] += e00 + e10;
                colp[nf][1] += e01 + e11;
            }
            rowp0[mf] = s0;
            rowp1[mf] = s1;
        }
        // row sums: reduce across the 4 lanes of a quad-row
#pragma unroll
        for (int mf = 0; mf < 4; mf++) {
            float s0 = rowp0[mf], s1 = rowp1[mf];
            s0 += __shfl_xor_sync(0xffffffffu, s0, 1);
            s0 += __shfl_xor_sync(0xffffffffu, s0, 2);
            s1 += __shfl_xor_sync(0xffffffffu, s1, 1);
            s1 += __shfl_xor_sync(0xffffffffu, s1, 2);
            if ((lid & 3) == 0) {
                int m = m0 + wm * 64 + mf * 16 + gr;
                atomicAdd(dr + bz * NQ + m, s0);
                atomicAdd(dr + bz * NQ + m + 8, s1);
            }
        }
        // col sums: reduce over gr (lid bits 2..4)
#pragma unroll
        for (int nf = 0; nf < 4; nf++)
#pragma unroll
            for (int t = 0; t < 2; t++) {
                float s = colp[nf][t];
                s += __shfl_xor_sync(0xffffffffu, s, 4);
                s += __shfl_xor_sync(0xffffffffu, s, 8);
                s += __shfl_xor_sync(0xffffffffu, s, 16);
                colp[nf][t] = s;
            }
        if (lid < 4) {
#pragma unroll
            for (int nf = 0; nf < 4; nf++) {
                int n = n0 + wn * 32 + nf * 8 + gc;
                atomicAdd(dc + bz * NV + n, colp[nf][0]);
                atomicAdd(dc + bz * NV + n + 1, colp[nf][1]);
            }
        }
    }
}

// ---------------- fused wq + wv: single pass over E --------------------------
// grid (NQ/128, B_), block 256. Warp w handles rows q0 + w*16 .. +15.
__global__ __launch_bounds__(256)
void wqwv_kernel(const float* __restrict__ dr, const float* __restrict__ dc,
                 float* __restrict__ wv) {
    __shared__ float2 sdc[NV / 2];
    int b = blockIdx.y, q0 = blockIdx.x * 128;
    int tid = threadIdx.x, w = tid >> 5, lane = tid & 31;
    for (int i = tid; i < NV / 2; i += 256) {
        sdc[i].x = 1.f / dc[b * NV + 2 * i];
        sdc[i].y = 1.f / dc[b * NV + 2 * i + 1];
    }
    __syncthreads();

    float colacc[32] = {};
#pragma unroll 1
    for (int r = 0; r < 16; r++) {
        int q = q0 + w * 16 + r;
        const __half2* row = (const __half2*)(g_E + (size_t)(b * NQ + q) * NV);
        float idr = 1.f / dr[b * NQ + q];
        float s = 0.f;
#pragma unroll
        for (int j = 0; j < 16; j++) {
            int idx = lane + j * 32;
            float2 v = __half22float2(row[idx]);
            float2 d = sdc[idx];
            s += v.x * d.x + v.y * d.y;
            colacc[2 * j]     += v.x * idr;
            colacc[2 * j + 1] += v.y * idr;
        }
#pragma unroll
        for (int o = 16; o; o >>= 1) s += __shfl_xor_sync(0xffffffffu, s, o);
        if (!lane) g_wq[b * NQ + q] = s;
    }
#pragma unroll
    for (int j = 0; j < 16; j++) {
        int idx = lane + j * 32;
        atomicAdd(wv + b * NV + 2 * idx, colacc[2 * j]);
        atomicAdd(wv + b * NV + 2 * idx + 1, colacc[2 * j + 1]);
    }
}

// ---------------- final pools (read fp16 Q/V) ---------------------------------
__global__ void vhat_kernel(const float* __restrict__ wv, float* __restrict__ out) {
    int b = blockIdx.x, d = threadIdx.x;
    const __half* Vb = g_Vf + (size_t)b * NV * VD;
    float s = 0.f;
#pragma unroll 4
    for (int v = 0; v < NV; v++) s += wv[b * NV + v] * __half2float(Vb[(size_t)v * VD + d]);
    out[b * VD + d] = s;
}

__global__ void qhat_kernel(float* __restrict__ out) {
    int b = blockIdx.x, d = threadIdx.x;
    const __half* Qb = g_Qf + (size_t)b * NQ * QD;
    float s = 0.f;
#pragma unroll 4
    for (int q = 0; q < NQ; q++) s += g_wq[b * NQ + q] * __half2float(Qb[(size_t)q * QD + d]);
    out[B_ * VD + b * QD + d] = s;
}

// ---------------- launch -----------------------------------------------------
extern "C" void kernel_launch(void* const* d_in, const int* in_sizes, int n_in,
                              void* d_out, int out_size) {
    const float* V  = (const float*)d_in[0];
    const float* Q  = (const float*)d_in[1];
    const float* Wq = (const float*)d_in[2];
    const float* bq = (const float*)d_in[3];
    const float* Wv = (const float*)d_in[4];
    const float* bv = (const float*)d_in[5];
    float* out = (float*)d_out;

    float *pa, *pc, *prq, *pcv, *pz;
    __half *pQf, *pVf, *pMTf, *pQMf, *pE;
    cudaGetSymbolAddress((void**)&pa, g_a);
    cudaGetSymbolAddress((void**)&pc, g_c);
    cudaGetSymbolAddress((void**)&prq, g_rq);
    cudaGetSymbolAddress((void**)&pcv, g_cv);
    cudaGetSymbolAddress((void**)&pz, g_zero);
    cudaGetSymbolAddress((void**)&pE, g_E);
    cudaGetSymbolAddress((void**)&pQf, g_Qf);
    cudaGetSymbolAddress((void**)&pVf, g_Vf);
    cudaGetSymbolAddress((void**)&pMTf, g_MTf);
    cudaGetSymbolAddress((void**)&pQMf, g_QMf);
    float* pdr = pz;
    float* pdc = pz + B_ * NQ;
    float* pwv = pz + B_ * NQ + B_ * NV;

    cudaFuncSetAttribute((const void*)mma_gemm<false>,
                         cudaFuncAttributeMaxDynamicSharedMemorySize, SMEM_DYN);
    cudaFuncSetAttribute((const void*)mma_gemm<true>,
                         cudaFuncAttributeMaxDynamicSharedMemorySize, SMEM_DYN);

    // 1) a, c, s0 + zero accumulators
    compute_ac<<<160, 1024>>>(Wq, Wv, bq, bv);
    // 2) MT[v,q] = sum_h Wv[h,v] * Wq[h,q]  -> fp16 directly
    gemm_tn_kernel<<<dim3(QD / 128, VD / 128, 1), 256>>>(Wv, Wq, pMTf, HIDD, VD, QD, QD);
    // 3) fused convert + row-dot (single read of Q and V)
    fuse_cvt_dot<QD, QD / 128, true><<<(B_ * NQ) / 8, 256>>>(Q, pQf, pa, prq);
    fuse_cvt_dot<VD, VD / 128, false><<<(B_ * NV) / 8, 256>>>(V, pVf, pc, pcv);
    // 4) QM = Q @ MT^T
    mma_gemm<false><<<dim3(VD / 128, (B_ * NQ) / 128, 1), 256, SMEM_DYN>>>(
        pQf, pMTf, QD, 0, 0, pQMf, VD, nullptr, nullptr, nullptr, nullptr, nullptr);
    // 5) E = exp(tanh(QM @ V^T + rq + cv)) -> fp16, + fused row/col sums
    mma_gemm<true><<<dim3(NV / 128, NQ / 128, B_), 256, SMEM_DYN>>>(
        pQMf, pVf, VD, (long long)NQ * VD, (long long)NV * VD,
        nullptr, 0, pE, prq, pcv, pdr, pdc);
    // 6) fused wq + wv (one pass over E)
    wqwv_kernel<<<dim3(NQ / 128, B_), 256>>>(pdr, pdc, pwv);
    // 7) pools
    vhat_kernel<<<B_, VD>>>(pwv, out);
    qhat_kernel<<<B_, QD>>>(out);
}

// round 8
// speedup vs baseline: 3.4176x; 1.2387x over previous
#include <cuda_runtime.h>
#include <cuda_fp16.h>
#include <cstdint>

#define B_   64
#define NQ   512
#define NV   1024
#define QD   768
#define VD   512
#define HIDD 512

// ---------------- scratch (device globals; no allocation allowed) ----------
__device__ __align__(16) float g_a[QD];
__device__ __align__(16) float g_c[VD];
__device__ float g_s0;
__device__ float g_rq[B_ * NQ];
__device__ float g_cv[B_ * NV];
__device__ __align__(16) __half g_Qf[(size_t)B_ * NQ * QD];
__device__ __align__(16) __half g_Vf[(size_t)B_ * NV * VD];
__device__ __align__(16) __half g_MTf[VD * QD];
__device__ __align__(16) __half g_QMf[(size_t)B_ * NQ * VD];
__device__ __align__(16) __half g_E[(size_t)B_ * NQ * NV];
// atomic accumulators (zeroed each call by compute_ac):
// [dr(B*NQ) | dc(B*NV) | wv(B*NV) | vh(B*VD) | qh(B*QD)]
#define ZN (B_ * NQ + 2 * B_ * NV + B_ * VD + B_ * QD)
__device__ float g_zero[ZN];
__device__ float g_wq[B_ * NQ];

// ---------------- PTX helpers (sm_80+ features only) ------------------------
__device__ __forceinline__ uint32_t smem_u32(const void* p) {
    uint32_t a;
    asm("{ .reg .u64 t; cvta.to.shared.u64 t, %1; cvt.u32.u64 %0, t; }" : "=r"(a) : "l"(p));
    return a;
}
__device__ __forceinline__ void cp16(uint32_t s, const void* g) {
    asm volatile("cp.async.cg.shared.global [%0], [%1], 16;" :: "r"(s), "l"(g));
}
__device__ __forceinline__ void cp_commit() { asm volatile("cp.async.commit_group;" ::: "memory"); }
__device__ __forceinline__ void cp_wait1()  { asm volatile("cp.async.wait_group 1;" ::: "memory"); }

__device__ __forceinline__ void ldm4(uint32_t a, uint32_t& r0, uint32_t& r1,
                                     uint32_t& r2, uint32_t& r3) {
    asm volatile("ldmatrix.sync.aligned.m8n8.x4.shared.b16 {%0,%1,%2,%3}, [%4];"
                 : "=r"(r0), "=r"(r1), "=r"(r2), "=r"(r3) : "r"(a));
}
__device__ __forceinline__ void mma16816(float& c0, float& c1, float& c2, float& c3,
                                         uint32_t a0, uint32_t a1, uint32_t a2, uint32_t a3,
                                         uint32_t b0, uint32_t b1) {
    asm volatile("mma.sync.aligned.m16n8k16.row.col.f32.f16.f16.f32 "
                 "{%0,%1,%2,%3}, {%4,%5,%6,%7}, {%8,%9}, {%0,%1,%2,%3};"
                 : "+f"(c0), "+f"(c1), "+f"(c2), "+f"(c3)
                 : "r"(a0), "r"(a1), "r"(a2), "r"(a3), "r"(b0), "r"(b1));
}

// ---------------- precompute a, c, s0 + zero the atomic accumulators --------
__global__ void compute_ac(const float* __restrict__ Wq, const float* __restrict__ Wv,
                           const float* __restrict__ bq, const float* __restrict__ bv) {
    int t = blockIdx.x * 1024 + threadIdx.x;
    if (t < ZN) g_zero[t] = 0.f;
    if (t < QD) {
        float s = 0.f;
        for (int h = 0; h < HIDD; h++) s += Wq[h * QD + t] * bv[h];
        g_a[t] = s;
    } else if (t < QD + VD) {
        int e = t - QD;
        float s = 0.f;
        for (int h = 0; h < HIDD; h++) s += Wv[h * VD + e] * bq[h];
        g_c[e] = s;
    } else if (t == QD + VD) {
        float s = 0.f;
        for (int h = 0; h < HIDD; h++) s += bq[h] * bv[h];
        g_s0 = s;
    }
}

// ---------------- fused fp32->fp16 convert + row-dot -------------------------
template <int K, int NF4, bool ADD_S0>
__global__ void fuse_cvt_dot(const float* __restrict__ X, __half* __restrict__ Xf,
                             const float* __restrict__ vec, float* __restrict__ out) {
    int row = blockIdx.x * 8 + (threadIdx.x >> 5);
    int lane = threadIdx.x & 31;
    const float4* xr = (const float4*)(X + (size_t)row * K);
    const float4* vr = (const float4*)vec;
    __half2* hr = (__half2*)(Xf + (size_t)row * K);
    float s = 0.f;
#pragma unroll
    for (int j = 0; j < NF4; j++) {
        int idx = lane + j * 32;
        float4 v = xr[idx];
        float4 a = vr[idx];
        s += v.x * a.x + v.y * a.y + v.z * a.z + v.w * a.w;
        hr[2 * idx]     = __floats2half2_rn(v.x, v.y);
        hr[2 * idx + 1] = __floats2half2_rn(v.z, v.w);
    }
#pragma unroll
    for (int o = 16; o; o >>= 1) s += __shfl_xor_sync(0xffffffffu, s, o);
    if (!lane) out[row] = s + (ADD_S0 ? g_s0 : 0.f);
}

// ---------------- fp32 GEMM -> fp16 out (tiny MT = Wv^T Wq) ------------------
__global__ __launch_bounds__(256)
void gemm_tn_kernel(const float* __restrict__ A, const float* __restrict__ B,
                    __half* __restrict__ C, int K, int lda, int ldb, int ldc) {
    const int BM = 128, BN = 128, BK = 8;
    const int m0 = blockIdx.y * BM, n0 = blockIdx.x * BN;
    __shared__ float As[BK][BM + 4];
    __shared__ float Bs[BK][BN + 4];
    const int tid = threadIdx.x;
    const int tx = tid & 15, ty = tid >> 4;
    float acc[8][8];
#pragma unroll
    for (int i = 0; i < 8; i++)
#pragma unroll
        for (int j = 0; j < 8; j++) acc[i][j] = 0.f;
    for (int k0 = 0; k0 < K; k0 += BK) {
        {
            int k = tid >> 5, m4 = (tid & 31) * 4;
            *(float4*)&As[k][m4] = *(const float4*)&A[(size_t)(k0 + k) * lda + m0 + m4];
        }
        {
            int k = tid >> 5, n4 = (tid & 31) * 4;
            *(float4*)&Bs[k][n4] = *(const float4*)&B[(size_t)(k0 + k) * ldb + n0 + n4];
        }
        __syncthreads();
#pragma unroll
        for (int k = 0; k < BK; k++) {
            float4 a0 = *(const float4*)&As[k][ty * 8];
            float4 a1 = *(const float4*)&As[k][ty * 8 + 4];
            float4 b0 = *(const float4*)&Bs[k][tx * 8];
            float4 b1 = *(const float4*)&Bs[k][tx * 8 + 4];
            float ar[8] = {a0.x, a0.y, a0.z, a0.w, a1.x, a1.y, a1.z, a1.w};
            float br[8] = {b0.x, b0.y, b0.z, b0.w, b1.x, b1.y, b1.z, b1.w};
#pragma unroll
            for (int i = 0; i < 8; i++)
#pragma unroll
                for (int j = 0; j < 8; j++) acc[i][j] += ar[i] * br[j];
        }
        __syncthreads();
    }
#pragma unroll
    for (int i = 0; i < 8; i++) {
        int m = m0 + ty * 8 + i;
        __half2* cptr = (__half2*)&C[(size_t)m * ldc + n0 + tx * 8];
#pragma unroll
        for (int j = 0; j < 4; j++)
            cptr[j] = __floats2half2_rn(acc[i][2 * j], acc[i][2 * j + 1]);
    }
}

// ---------------- mma.sync fp16 GEMM, 128x128x32, 3-stage pipeline ----------
#define STG_BYTES 20480   // A tile 128*80 + B tile 128*80
#define SMEM_DYN  (3 * STG_BYTES)

__device__ __forceinline__ void load_stage(uint32_t sb, const __half* pa,
                                           const __half* pb, int m0, int n0,
                                           int kk, int K, int r, int c) {
    const __half* ga = pa + (size_t)(m0 + r) * K + kk + c * 8;
    cp16(sb + r * 80 + c * 16, ga);
    cp16(sb + (r + 64) * 80 + c * 16, ga + (size_t)64 * K);
    const __half* gb = pb + (size_t)(n0 + r) * K + kk + c * 8;
    cp16(sb + 10240 + r * 80 + c * 16, gb);
    cp16(sb + 10240 + (r + 64) * 80 + c * 16, gb + (size_t)64 * K);
}

// EPI=false: C = fp16(acc).  EPI=true: E=fp16(exp(tanh(acc+rq+cv))) + atomic row/col sums.
template <bool EPI>
__global__ __launch_bounds__(256, 1)
void mma_gemm(const __half* __restrict__ A, const __half* __restrict__ B,
              int K, long long sA, long long sB,
              __half* __restrict__ C, int ldc,
              __half* __restrict__ E, const float* __restrict__ rq, const float* __restrict__ cv,
              float* __restrict__ dr, float* __restrict__ dc) {
    extern __shared__ __align__(128) uint8_t smbuf[];
    const int tid = threadIdx.x, lid = tid & 31, wid = tid >> 5;
    const int wm = wid >> 2, wn = wid & 3;   // 2 x 4 warp grid
    const int m0 = blockIdx.y * 128, n0 = blockIdx.x * 128, bz = blockIdx.z;
    A += (size_t)bz * sA;
    B += (size_t)bz * sB;

    const int T = K / 32;
    const int lr = tid >> 2, lc = tid & 3;   // loader row/chunk

    float acc[4][4][4] = {};
    uint32_t sb0 = smem_u32(smbuf);

#pragma unroll
    for (int i = 0; i < 2; i++) {
        load_stage(sb0 + i * STG_BYTES, A, B, m0, n0, i * 32, K, lr, lc);
        cp_commit();
    }

    for (int i = 0; i < T; i++) {
        cp_wait1();
        __syncthreads();
        if (i + 2 < T) {
            int s = (i + 2) % 3;
            load_stage(sb0 + s * STG_BYTES, A, B, m0, n0, (i + 2) * 32, K, lr, lc);
        }
        cp_commit();
        uint32_t sb = sb0 + (i % 3) * STG_BYTES;

        uint32_t Af[2][4][4], Bf[2][2][4];
#pragma unroll
        for (int ks = 0; ks < 2; ks++) {
#pragma unroll
            for (int mf = 0; mf < 4; mf++) {
                int row = wm * 64 + mf * 16 + (lid & 15);
                int ch = ks * 2 + (lid >> 4);
                ldm4(sb + row * 80 + ch * 16,
                     Af[ks][mf][0], Af[ks][mf][1], Af[ks][mf][2], Af[ks][mf][3]);
            }
#pragma unroll
            for (int np = 0; np < 2; np++) {
                int g = lid >> 3;
                int row = wn * 32 + np * 16 + ((g >> 1) << 3) + (lid & 7);
                int ch = ks * 2 + (g & 1);
                ldm4(sb + 10240 + row * 80 + ch * 16,
                     Bf[ks][np][0], Bf[ks][np][1], Bf[ks][np][2], Bf[ks][np][3]);
            }
        }
#pragma unroll
        for (int ks = 0; ks < 2; ks++)
#pragma unroll
            for (int mf = 0; mf < 4; mf++)
#pragma unroll
                for (int nf = 0; nf < 4; nf++) {
                    uint32_t b0 = Bf[ks][nf >> 1][(nf & 1) * 2];
                    uint32_t b1 = Bf[ks][nf >> 1][(nf & 1) * 2 + 1];
                    mma16816(acc[mf][nf][0], acc[mf][nf][1], acc[mf][nf][2], acc[mf][nf][3],
                             Af[ks][mf][0], Af[ks][mf][1], Af[ks][mf][2], Af[ks][mf][3],
                             b0, b1);
                }
    }

    // epilogue
    const int gr = lid >> 2, gc = (lid & 3) * 2;
    if (!EPI) {
#pragma unroll
        for (int mf = 0; mf < 4; mf++) {
            int m = m0 + wm * 64 + mf * 16 + gr;
#pragma unroll
            for (int nf = 0; nf < 4; nf++) {
                int n = n0 + wn * 32 + nf * 8 + gc;
                *(__half2*)(C + (size_t)m * ldc + n) =
                    __floats2half2_rn(acc[mf][nf][0], acc[mf][nf][1]);
                *(__half2*)(C + (size_t)(m + 8) * ldc + n) =
                    __floats2half2_rn(acc[mf][nf][2], acc[mf][nf][3]);
            }
        }
    } else {
        float colp[4][2] = {};
        float rowp0[4], rowp1[4];
#pragma unroll
        for (int mf = 0; mf < 4; mf++) {
            int m = m0 + wm * 64 + mf * 16 + gr;
            float r0v = rq[bz * NQ + m], r1v = rq[bz * NQ + m + 8];
            float s0 = 0.f, s1 = 0.f;
#pragma unroll
            for (int nf = 0; nf < 4; nf++) {
                int n = n0 + wn * 32 + nf * 8 + gc;
                float cv0 = cv[bz * NV + n], cv1 = cv[bz * NV + n + 1];
                float e00 = __expf(tanhf(acc[mf][nf][0] + r0v + cv0));
                float e01 = __expf(tanhf(acc[mf][nf][1] + r0v + cv1));
                float e10 = __expf(tanhf(acc[mf][nf][2] + r1v + cv0));
                float e11 = __expf(tanhf(acc[mf][nf][3] + r1v + cv1));
                size_t e0 = (size_t)bz * NQ * NV + (size_t)m * NV + n;
                *(__half2*)(E + e0) = __floats2half2_rn(e00, e01);
                *(__half2*)(E + e0 + (size_t)8 * NV) = __floats2half2_rn(e10, e11);
                s0 += e00 + e01;
                s1 += e10 + e11;
                colp[nf][0] += e00 + e10;
                colp[nf][1] += e01 + e11;
            }
            rowp0[mf] = s0;
            rowp1[mf] = s1;
        }
#pragma unroll
        for (int mf = 0; mf < 4; mf++) {
            float s0 = rowp0[mf], s1 = rowp1[mf];
            s0 += __shfl_xor_sync(0xffffffffu, s0, 1);
            s0 += __shfl_xor_sync(0xffffffffu, s0, 2);
            s1 += __shfl_xor_sync(0xffffffffu, s1, 1);
            s1 += __shfl_xor_sync(0xffffffffu, s1, 2);
            if ((lid & 3) == 0) {
                int m = m0 + wm * 64 + mf * 16 + gr;
                atomicAdd(dr + bz * NQ + m, s0);
                atomicAdd(dr + bz * NQ + m + 8, s1);
            }
        }
#pragma unroll
        for (int nf = 0; nf < 4; nf++)
#pragma unroll
            for (int t = 0; t < 2; t++) {
                float s = colp[nf][t];
                s += __shfl_xor_sync(0xffffffffu, s, 4);
                s += __shfl_xor_sync(0xffffffffu, s, 8);
                s += __shfl_xor_sync(0xffffffffu, s, 16);
                colp[nf][t] = s;
            }
        if (lid < 4) {
#pragma unroll
            for (int nf = 0; nf < 4; nf++) {
                int n = n0 + wn * 32 + nf * 8 + gc;
                atomicAdd(dc + bz * NV + n, colp[nf][0]);
                atomicAdd(dc + bz * NV + n + 1, colp[nf][1]);
            }
        }
    }
}

// ---------------- fused wq + wv: single pass over E --------------------------
__global__ __launch_bounds__(256)
void wqwv_kernel(const float* __restrict__ dr, const float* __restrict__ dc,
                 float* __restrict__ wv) {
    __shared__ float2 sdc[NV / 2];
    int b = blockIdx.y, q0 = blockIdx.x * 128;
    int tid = threadIdx.x, w = tid >> 5, lane = tid & 31;
    for (int i = tid; i < NV / 2; i += 256) {
        sdc[i].x = 1.f / dc[b * NV + 2 * i];
        sdc[i].y = 1.f / dc[b * NV + 2 * i + 1];
    }
    __syncthreads();

    float colacc[32] = {};
#pragma unroll 1
    for (int r = 0; r < 16; r++) {
        int q = q0 + w * 16 + r;
        const __half2* row = (const __half2*)(g_E + (size_t)(b * NQ + q) * NV);
        float idr = 1.f / dr[b * NQ + q];
        float s = 0.f;
#pragma unroll
        for (int j = 0; j < 16; j++) {
            int idx = lane + j * 32;
            float2 v = __half22float2(row[idx]);
            float2 d = sdc[idx];
            s += v.x * d.x + v.y * d.y;
            colacc[2 * j]     += v.x * idr;
            colacc[2 * j + 1] += v.y * idr;
        }
#pragma unroll
        for (int o = 16; o; o >>= 1) s += __shfl_xor_sync(0xffffffffu, s, o);
        if (!lane) g_wq[b * NQ + q] = s;
    }
#pragma unroll
    for (int j = 0; j < 16; j++) {
        int idx = lane + j * 32;
        atomicAdd(wv + b * NV + 2 * idx, colacc[2 * j]);
        atomicAdd(wv + b * NV + 2 * idx + 1, colacc[2 * j + 1]);
    }
}

// ---------------- final pools: 4-way split + atomic partials ------------------
__global__ void vhat_kernel(const float* __restrict__ wv, float* __restrict__ vh) {
    int b = blockIdx.x, part = blockIdx.y, d = threadIdx.x;
    const __half* Vb = g_Vf + (size_t)b * NV * VD + (size_t)part * (NV / 4) * VD;
    const float* w = wv + b * NV + part * (NV / 4);
    float s = 0.f;
#pragma unroll 4
    for (int v = 0; v < NV / 4; v++) s += w[v] * __half2float(Vb[(size_t)v * VD + d]);
    atomicAdd(vh + b * VD + d, s);
}

__global__ void qhat_kernel(float* __restrict__ qh) {
    int b = blockIdx.x, part = blockIdx.y, d = threadIdx.x;
    const __half* Qb = g_Qf + (size_t)b * NQ * QD + (size_t)part * (NQ / 4) * QD;
    const float* w = g_wq + b * NQ + part * (NQ / 4);
    float s = 0.f;
#pragma unroll 4
    for (int q = 0; q < NQ / 4; q++) s += w[q] * __half2float(Qb[(size_t)q * QD + d]);
    atomicAdd(qh + b * QD + d, s);
}

__global__ void writeout_kernel(const float* __restrict__ vh, const float* __restrict__ qh,
                                float* __restrict__ out) {
    int i = blockIdx.x * 256 + threadIdx.x;
    int NOUT = B_ * VD + B_ * QD;
    if (i >= NOUT) return;
    out[i] = (i < B_ * VD) ? vh[i] : qh[i - B_ * VD];
}

// ---------------- launch -----------------------------------------------------
extern "C" void kernel_launch(void* const* d_in, const int* in_sizes, int n_in,
                              void* d_out, int out_size) {
    const float* V  = (const float*)d_in[0];
    const float* Q  = (const float*)d_in[1];
    const float* Wq = (const float*)d_in[2];
    const float* bq = (const float*)d_in[3];
    const float* Wv = (const float*)d_in[4];
    const float* bv = (const float*)d_in[5];
    float* out = (float*)d_out;

    float *pa, *pc, *prq, *pcv, *pz;
    __half *pQf, *pVf, *pMTf, *pQMf, *pE;
    cudaGetSymbolAddress((void**)&pa, g_a);
    cudaGetSymbolAddress((void**)&pc, g_c);
    cudaGetSymbolAddress((void**)&prq, g_rq);
    cudaGetSymbolAddress((void**)&pcv, g_cv);
    cudaGetSymbolAddress((void**)&pz, g_zero);
    cudaGetSymbolAddress((void**)&pE, g_E);
    cudaGetSymbolAddress((void**)&pQf, g_Qf);
    cudaGetSymbolAddress((void**)&pVf, g_Vf);
    cudaGetSymbolAddress((void**)&pMTf, g_MTf);
    cudaGetSymbolAddress((void**)&pQMf, g_QMf);
    float* pdr = pz;
    float* pdc = pz + B_ * NQ;
    float* pwv = pz + B_ * NQ + B_ * NV;
    float* pvh = pz + B_ * NQ + 2 * B_ * NV;
    float* pqh = pvh + B_ * VD;

    cudaFuncSetAttribute((const void*)mma_gemm<false>,
                         cudaFuncAttributeMaxDynamicSharedMemorySize, SMEM_DYN);
    cudaFuncSetAttribute((const void*)mma_gemm<true>,
                         cudaFuncAttributeMaxDynamicSharedMemorySize, SMEM_DYN);

    // 1) a, c, s0 + zero accumulators
    compute_ac<<<(ZN + 1023) / 1024, 1024>>>(Wq, Wv, bq, bv);
    // 2) MT[v,q] = sum_h Wv[h,v] * Wq[h,q]  -> fp16 directly
    gemm_tn_kernel<<<dim3(QD / 128, VD / 128, 1), 256>>>(Wv, Wq, pMTf, HIDD, VD, QD, QD);
    // 3) fused convert + row-dot for Q (needed by GEMM1)
    fuse_cvt_dot<QD, QD / 128, true><<<(B_ * NQ) / 8, 256>>>(Q, pQf, pa, prq);
    // 4) QM = Q @ MT^T   (4th launch -> gets the ncu capture)
    mma_gemm<false><<<dim3(VD / 128, (B_ * NQ) / 128, 1), 256, SMEM_DYN>>>(
        pQf, pMTf, QD, 0, 0, pQMf, VD, nullptr, nullptr, nullptr, nullptr, nullptr);
    // 5) fused convert + row-dot for V
    fuse_cvt_dot<VD, VD / 128, false><<<(B_ * NV) / 8, 256>>>(V, pVf, pc, pcv);
    // 6) E = exp(tanh(QM @ V^T + rq + cv)) -> fp16, + fused row/col sums
    mma_gemm<true><<<dim3(NV / 128, NQ / 128, B_), 256, SMEM_DYN>>>(
        pQMf, pVf, VD, (long long)NQ * VD, (long long)NV * VD,
        nullptr, 0, pE, prq, pcv, pdr, pdc);
    // 7) fused wq + wv (one pass over E)
    wqwv_kernel<<<dim3(NQ / 128, B_), 256>>>(pdr, pdc, pwv);
    // 8) pools (4-way parallel, atomic partials)
    vhat_kernel<<<dim3(B_, 4), VD>>>(pwv, pvh);
    qhat_kernel<<<dim3(B_, 4), QD>>>(pqh);
    // 9) writeout
    writeout_kernel<<<(B_ * VD + B_ * QD + 255) / 256, 256>>>(pvh, pqh, out);
}

// round 9
// speedup vs baseline: 4.0213x; 1.1767x over previous
#include <cuda_runtime.h>
#include <cuda_fp16.h>
#include <cstdint>

#define B_   64
#define NQ   512
#define NV   1024
#define QD   768
#define VD   512
#define HIDD 512

// ---------------- scratch (device globals; no allocation allowed) ----------
__device__ __align__(16) float g_a[QD];
__device__ __align__(16) float g_c[VD];
__device__ float g_s0;
__device__ float g_rq[B_ * NQ];
__device__ float g_cv[B_ * NV];
__device__ __align__(16) __half g_Qf[(size_t)B_ * NQ * QD];
__device__ __align__(16) __half g_Vf[(size_t)B_ * NV * VD];
__device__ __align__(16) __half g_MTf[VD * QD];
__device__ __align__(16) __half g_QMf[(size_t)B_ * NQ * VD];
__device__ __align__(16) __half g_E[(size_t)B_ * NQ * NV];
// atomic accumulators (zeroed each call by compute_ac):
// [dr(B*NQ) | dc(B*NV) | wv(B*NV) | vh(B*VD) | qh(B*QD)]
#define ZN (B_ * NQ + 2 * B_ * NV + B_ * VD + B_ * QD)
__device__ float g_zero[ZN];
__device__ float g_wq[B_ * NQ];

// ---------------- PTX helpers (sm_80+ features only) ------------------------
__device__ __forceinline__ uint32_t smem_u32(const void* p) {
    uint32_t a;
    asm("{ .reg .u64 t; cvta.to.shared.u64 t, %1; cvt.u32.u64 %0, t; }" : "=r"(a) : "l"(p));
    return a;
}
__device__ __forceinline__ void cp16(uint32_t s, const void* g) {
    asm volatile("cp.async.cg.shared.global [%0], [%1], 16;" :: "r"(s), "l"(g));
}
__device__ __forceinline__ void cp_commit() { asm volatile("cp.async.commit_group;" ::: "memory"); }
__device__ __forceinline__ void cp_wait1()  { asm volatile("cp.async.wait_group 1;" ::: "memory"); }

__device__ __forceinline__ void ldm4(uint32_t a, uint32_t& r0, uint32_t& r1,
                                     uint32_t& r2, uint32_t& r3) {
    asm volatile("ldmatrix.sync.aligned.m8n8.x4.shared.b16 {%0,%1,%2,%3}, [%4];"
                 : "=r"(r0), "=r"(r1), "=r"(r2), "=r"(r3) : "r"(a));
}
__device__ __forceinline__ void mma16816(float& c0, float& c1, float& c2, float& c3,
                                         uint32_t a0, uint32_t a1, uint32_t a2, uint32_t a3,
                                         uint32_t b0, uint32_t b1) {
    asm volatile("mma.sync.aligned.m16n8k16.row.col.f32.f16.f16.f32 "
                 "{%0,%1,%2,%3}, {%4,%5,%6,%7}, {%8,%9}, {%0,%1,%2,%3};"
                 : "+f"(c0), "+f"(c1), "+f"(c2), "+f"(c3)
                 : "r"(a0), "r"(a1), "r"(a2), "r"(a3), "r"(b0), "r"(b1));
}

// ---------------- precompute a, c, s0 + zero the atomic accumulators --------
__global__ void compute_ac(const float* __restrict__ Wq, const float* __restrict__ Wv,
                           const float* __restrict__ bq, const float* __restrict__ bv) {
    int t = blockIdx.x * 1024 + threadIdx.x;
    if (t < ZN) g_zero[t] = 0.f;
    if (t < QD) {
        float s = 0.f;
        for (int h = 0; h < HIDD; h++) s += Wq[h * QD + t] * bv[h];
        g_a[t] = s;
    } else if (t < QD + VD) {
        int e = t - QD;
        float s = 0.f;
        for (int h = 0; h < HIDD; h++) s += Wv[h * VD + e] * bq[h];
        g_c[e] = s;
    } else if (t == QD + VD) {
        float s = 0.f;
        for (int h = 0; h < HIDD; h++) s += bq[h] * bv[h];
        g_s0 = s;
    }
}

// ---------------- fused fp32->fp16 convert + row-dot -------------------------
template <int K, int NF4, bool ADD_S0>
__global__ void fuse_cvt_dot(const float* __restrict__ X, __half* __restrict__ Xf,
                             const float* __restrict__ vec, float* __restrict__ out) {
    int row = blockIdx.x * 8 + (threadIdx.x >> 5);
    int lane = threadIdx.x & 31;
    const float4* xr = (const float4*)(X + (size_t)row * K);
    const float4* vr = (const float4*)vec;
    __half2* hr = (__half2*)(Xf + (size_t)row * K);
    float s = 0.f;
#pragma unroll
    for (int j = 0; j < NF4; j++) {
        int idx = lane + j * 32;
        float4 v = xr[idx];
        float4 a = vr[idx];
        s += v.x * a.x + v.y * a.y + v.z * a.z + v.w * a.w;
        hr[2 * idx]     = __floats2half2_rn(v.x, v.y);
        hr[2 * idx + 1] = __floats2half2_rn(v.z, v.w);
    }
#pragma unroll
    for (int o = 16; o; o >>= 1) s += __shfl_xor_sync(0xffffffffu, s, o);
    if (!lane) out[row] = s + (ADD_S0 ? g_s0 : 0.f);
}

// ---------------- fp32 GEMM -> fp16 out (tiny MT = Wv^T Wq) ------------------
__global__ __launch_bounds__(256)
void gemm_tn_kernel(const float* __restrict__ A, const float* __restrict__ B,
                    __half* __restrict__ C, int K, int lda, int ldb, int ldc) {
    const int BM = 128, BN = 128, BK = 8;
    const int m0 = blockIdx.y * BM, n0 = blockIdx.x * BN;
    __shared__ float As[BK][BM + 4];
    __shared__ float Bs[BK][BN + 4];
    const int tid = threadIdx.x;
    const int tx = tid & 15, ty = tid >> 4;
    float acc[8][8];
#pragma unroll
    for (int i = 0; i < 8; i++)
#pragma unroll
        for (int j = 0; j < 8; j++) acc[i][j] = 0.f;
    for (int k0 = 0; k0 < K; k0 += BK) {
        {
            int k = tid >> 5, m4 = (tid & 31) * 4;
            *(float4*)&As[k][m4] = *(const float4*)&A[(size_t)(k0 + k) * lda + m0 + m4];
        }
        {
            int k = tid >> 5, n4 = (tid & 31) * 4;
            *(float4*)&Bs[k][n4] = *(const float4*)&B[(size_t)(k0 + k) * ldb + n0 + n4];
        }
        __syncthreads();
#pragma unroll
        for (int k = 0; k < BK; k++) {
            float4 a0 = *(const float4*)&As[k][ty * 8];
            float4 a1 = *(const float4*)&As[k][ty * 8 + 4];
            float4 b0 = *(const float4*)&Bs[k][tx * 8];
            float4 b1 = *(const float4*)&Bs[k][tx * 8 + 4];
            float ar[8] = {a0.x, a0.y, a0.z, a0.w, a1.x, a1.y, a1.z, a1.w};
            float br[8] = {b0.x, b0.y, b0.z, b0.w, b1.x, b1.y, b1.z, b1.w};
#pragma unroll
            for (int i = 0; i < 8; i++)
#pragma unroll
                for (int j = 0; j < 8; j++) acc[i][j] += ar[i] * br[j];
        }
        __syncthreads();
    }
#pragma unroll
    for (int i = 0; i < 8; i++) {
        int m = m0 + ty * 8 + i;
        __half2* cptr = (__half2*)&C[(size_t)m * ldc + n0 + tx * 8];
#pragma unroll
        for (int j = 0; j < 4; j++)
            cptr[j] = __floats2half2_rn(acc[i][2 * j], acc[i][2 * j + 1]);
    }
}

// ---------------- mma.sync fp16 GEMM, 128x128x32, 3-stage, 2 CTAs/SM ---------
#define STG_BYTES 20480   // A tile 128*80 + B tile 128*80
#define SMEM_DYN  (3 * STG_BYTES)

__device__ __forceinline__ void load_stage(uint32_t sb, const __half* pa,
                                           const __half* pb, int m0, int n0,
                                           int kk, int K, int r, int c) {
    const __half* ga = pa + (size_t)(m0 + r) * K + kk + c * 8;
    cp16(sb + r * 80 + c * 16, ga);
    cp16(sb + (r + 64) * 80 + c * 16, ga + (size_t)64 * K);
    const __half* gb = pb + (size_t)(n0 + r) * K + kk + c * 8;
    cp16(sb + 10240 + r * 80 + c * 16, gb);
    cp16(sb + 10240 + (r + 64) * 80 + c * 16, gb + (size_t)64 * K);
}

// EPI=false: C = fp16(acc).  EPI=true: E=fp16(exp(tanh(acc+rq+cv))) + atomic row/col sums.
template <bool EPI>
__global__ __launch_bounds__(256, 2)
void mma_gemm(const __half* __restrict__ A, const __half* __restrict__ B,
              int K, long long sA, long long sB,
              __half* __restrict__ C, int ldc,
              __half* __restrict__ E, const float* __restrict__ rq, const float* __restrict__ cv,
              float* __restrict__ dr, float* __restrict__ dc) {
    extern __shared__ __align__(128) uint8_t smbuf[];
    const int tid = threadIdx.x, lid = tid & 31, wid = tid >> 5;
    const int wm = wid >> 2, wn = wid & 3;   // 2 x 4 warp grid
    const int m0 = blockIdx.y * 128, n0 = blockIdx.x * 128, bz = blockIdx.z;
    A += (size_t)bz * sA;
    B += (size_t)bz * sB;

    const int T = K / 32;
    const int lr = tid >> 2, lc = tid & 3;   // loader row/chunk

    float acc[4][4][4] = {};
    uint32_t sb0 = smem_u32(smbuf);

#pragma unroll
    for (int i = 0; i < 2; i++) {
        load_stage(sb0 + i * STG_BYTES, A, B, m0, n0, i * 32, K, lr, lc);
        cp_commit();
    }

    for (int i = 0; i < T; i++) {
        cp_wait1();
        __syncthreads();
        if (i + 2 < T) {
            int s = (i + 2) % 3;
            load_stage(sb0 + s * STG_BYTES, A, B, m0, n0, (i + 2) * 32, K, lr, lc);
        }
        cp_commit();
        uint32_t sb = sb0 + (i % 3) * STG_BYTES;

        // per-halfstep fragments: fewer live regs -> 2 CTAs/SM
#pragma unroll
        for (int ks = 0; ks < 2; ks++) {
            uint32_t Af[4][4], Bf[2][4];
#pragma unroll
            for (int mf = 0; mf < 4; mf++) {
                int row = wm * 64 + mf * 16 + (lid & 15);
                int ch = ks * 2 + (lid >> 4);
                ldm4(sb + row * 80 + ch * 16,
                     Af[mf][0], Af[mf][1], Af[mf][2], Af[mf][3]);
            }
#pragma unroll
            for (int np = 0; np < 2; np++) {
                int g = lid >> 3;
                int row = wn * 32 + np * 16 + ((g >> 1) << 3) + (lid & 7);
                int ch = ks * 2 + (g & 1);
                ldm4(sb + 10240 + row * 80 + ch * 16,
                     Bf[np][0], Bf[np][1], Bf[np][2], Bf[np][3]);
            }
#pragma unroll
            for (int mf = 0; mf < 4; mf++)
#pragma unroll
                for (int nf = 0; nf < 4; nf++) {
                    uint32_t b0 = Bf[nf >> 1][(nf & 1) * 2];
                    uint32_t b1 = Bf[nf >> 1][(nf & 1) * 2 + 1];
                    mma16816(acc[mf][nf][0], acc[mf][nf][1], acc[mf][nf][2], acc[mf][nf][3],
                             Af[mf][0], Af[mf][1], Af[mf][2], Af[mf][3],
                             b0, b1);
                }
        }
    }

    // epilogue
    const int gr = lid >> 2, gc = (lid & 3) * 2;
    if (!EPI) {
#pragma unroll
        for (int mf = 0; mf < 4; mf++) {
            int m = m0 + wm * 64 + mf * 16 + gr;
#pragma unroll
            for (int nf = 0; nf < 4; nf++) {
                int n = n0 + wn * 32 + nf * 8 + gc;
                *(__half2*)(C + (size_t)m * ldc + n) =
                    __floats2half2_rn(acc[mf][nf][0], acc[mf][nf][1]);
                *(__half2*)(C + (size_t)(m + 8) * ldc + n) =
                    __floats2half2_rn(acc[mf][nf][2], acc[mf][nf][3]);
            }
        }
    } else {
        float colp[4][2] = {};
        float rowp0[4], rowp1[4];
#pragma unroll
        for (int mf = 0; mf < 4; mf++) {
            int m = m0 + wm * 64 + mf * 16 + gr;
            float r0v = rq[bz * NQ + m], r1v = rq[bz * NQ + m + 8];
            float s0 = 0.f, s1 = 0.f;
#pragma unroll
            for (int nf = 0; nf < 4; nf++) {
                int n = n0 + wn * 32 + nf * 8 + gc;
                float cv0 = cv[bz * NV + n], cv1 = cv[bz * NV + n + 1];
                float e00 = __expf(tanhf(acc[mf][nf][0] + r0v + cv0));
                float e01 = __expf(tanhf(acc[mf][nf][1] + r0v + cv1));
                float e10 = __expf(tanhf(acc[mf][nf][2] + r1v + cv0));
                float e11 = __expf(tanhf(acc[mf][nf][3] + r1v + cv1));
                size_t e0 = (size_t)bz * NQ * NV + (size_t)m * NV + n;
                *(__half2*)(E + e0) = __floats2half2_rn(e00, e01);
                *(__half2*)(E + e0 + (size_t)8 * NV) = __floats2half2_rn(e10, e11);
                s0 += e00 + e01;
                s1 += e10 + e11;
                colp[nf][0] += e00 + e10;
                colp[nf][1] += e01 + e11;
            }
            rowp0[mf] = s0;
            rowp1[mf] = s1;
        }
#pragma unroll
        for (int mf = 0; mf < 4; mf++) {
            float s0 = rowp0[mf], s1 = rowp1[mf];
            s0 += __shfl_xor_sync(0xffffffffu, s0, 1);
            s0 += __shfl_xor_sync(0xffffffffu, s0, 2);
            s1 += __shfl_xor_sync(0xffffffffu, s1, 1);
            s1 += __shfl_xor_sync(0xffffffffu, s1, 2);
            if ((lid & 3) == 0) {
                int m = m0 + wm * 64 + mf * 16 + gr;
                atomicAdd(dr + bz * NQ + m, s0);
                atomicAdd(dr + bz * NQ + m + 8, s1);
            }
        }
#pragma unroll
        for (int nf = 0; nf < 4; nf++)
#pragma unroll
            for (int t = 0; t < 2; t++) {
                float s = colp[nf][t];
                s += __shfl_xor_sync(0xffffffffu, s, 4);
                s += __shfl_xor_sync(0xffffffffu, s, 8);
                s += __shfl_xor_sync(0xffffffffu, s, 16);
                colp[nf][t] = s;
            }
        if (lid < 4) {
#pragma unroll
            for (int nf = 0; nf < 4; nf++) {
                int n = n0 + wn * 32 + nf * 8 + gc;
                atomicAdd(dc + bz * NV + n, colp[nf][0]);
                atomicAdd(dc + bz * NV + n + 1, colp[nf][1]);
            }
        }
    }
}

// ---------------- fused wq + wv: single pass over E --------------------------
__global__ __launch_bounds__(256)
void wqwv_kernel(const float* __restrict__ dr, const float* __restrict__ dc,
                 float* __restrict__ wv) {
    __shared__ float2 sdc[NV / 2];
    int b = blockIdx.y, q0 = blockIdx.x * 128;
    int tid = threadIdx.x, w = tid >> 5, lane = tid & 31;
    for (int i = tid; i < NV / 2; i += 256) {
        sdc[i].x = 1.f / dc[b * NV + 2 * i];
        sdc[i].y = 1.f / dc[b * NV + 2 * i + 1];
    }
    __syncthreads();

    float colacc[32] = {};
#pragma unroll 1
    for (int r = 0; r < 16; r++) {
        int q = q0 + w * 16 + r;
        const __half2* row = (const __half2*)(g_E + (size_t)(b * NQ + q) * NV);
        float idr = 1.f / dr[b * NQ + q];
        float s = 0.f;
#pragma unroll
        for (int j = 0; j < 16; j++) {
            int idx = lane + j * 32;
            float2 v = __half22float2(row[idx]);
            float2 d = sdc[idx];
            s += v.x * d.x + v.y * d.y;
            colacc[2 * j]     += v.x * idr;
            colacc[2 * j + 1] += v.y * idr;
        }
#pragma unroll
        for (int o = 16; o; o >>= 1) s += __shfl_xor_sync(0xffffffffu, s, o);
        if (!lane) g_wq[b * NQ + q] = s;
    }
#pragma unroll
    for (int j = 0; j < 16; j++) {
        int idx = lane + j * 32;
        atomicAdd(wv + b * NV + 2 * idx, colacc[2 * j]);
        atomicAdd(wv + b * NV + 2 * idx + 1, colacc[2 * j + 1]);
    }
}

// ---------------- final pools: 4-way split + atomic partials ------------------
__global__ void vhat_kernel(const float* __restrict__ wv, float* __restrict__ vh) {
    int b = blockIdx.x, part = blockIdx.y, d = threadIdx.x;
    const __half* Vb = g_Vf + (size_t)b * NV * VD + (size_t)part * (NV / 4) * VD;
    const float* w = wv + b * NV + part * (NV / 4);
    float s = 0.f;
#pragma unroll 4
    for (int v = 0; v < NV / 4; v++) s += w[v] * __half2float(Vb[(size_t)v * VD + d]);
    atomicAdd(vh + b * VD + d, s);
}

__global__ void qhat_kernel(float* __restrict__ qh) {
    int b = blockIdx.x, part = blockIdx.y, d = threadIdx.x;
    const __half* Qb = g_Qf + (size_t)b * NQ * QD + (size_t)part * (NQ / 4) * QD;
    const float* w = g_wq + b * NQ + part * (NQ / 4);
    float s = 0.f;
#pragma unroll 4
    for (int q = 0; q < NQ / 4; q++) s += w[q] * __half2float(Qb[(size_t)q * QD + d]);
    atomicAdd(qh + b * QD + d, s);
}

__global__ void writeout_kernel(const float* __restrict__ vh, const float* __restrict__ qh,
                                float* __restrict__ out) {
    int i = blockIdx.x * 256 + threadIdx.x;
    int NOUT = B_ * VD + B_ * QD;
    if (i >= NOUT) return;
    out[i] = (i < B_ * VD) ? vh[i] : qh[i - B_ * VD];
}

// ---------------- launch -----------------------------------------------------
extern "C" void kernel_launch(void* const* d_in, const int* in_sizes, int n_in,
                              void* d_out, int out_size) {
    const float* V  = (const float*)d_in[0];
    const float* Q  = (const float*)d_in[1];
    const float* Wq = (const float*)d_in[2];
    const float* bq = (const float*)d_in[3];
    const float* Wv = (const float*)d_in[4];
    const float* bv = (const float*)d_in[5];
    float* out = (float*)d_out;

    float *pa, *pc, *prq, *pcv, *pz;
    __half *pQf, *pVf, *pMTf, *pQMf, *pE;
    cudaGetSymbolAddress((void**)&pa, g_a);
    cudaGetSymbolAddress((void**)&pc, g_c);
    cudaGetSymbolAddress((void**)&prq, g_rq);
    cudaGetSymbolAddress((void**)&pcv, g_cv);
    cudaGetSymbolAddress((void**)&pz, g_zero);
    cudaGetSymbolAddress((void**)&pE, g_E);
    cudaGetSymbolAddress((void**)&pQf, g_Qf);
    cudaGetSymbolAddress((void**)&pVf, g_Vf);
    cudaGetSymbolAddress((void**)&pMTf, g_MTf);
    cudaGetSymbolAddress((void**)&pQMf, g_QMf);
    float* pdr = pz;
    float* pdc = pz + B_ * NQ;
    float* pwv = pz + B_ * NQ + B_ * NV;
    float* pvh = pz + B_ * NQ + 2 * B_ * NV;
    float* pqh = pvh + B_ * VD;

    cudaFuncSetAttribute((const void*)mma_gemm<false>,
                         cudaFuncAttributeMaxDynamicSharedMemorySize, SMEM_DYN);
    cudaFuncSetAttribute((const void*)mma_gemm<true>,
                         cudaFuncAttributeMaxDynamicSharedMemorySize, SMEM_DYN);

    // 1) a, c, s0 + zero accumulators
    compute_ac<<<(ZN + 1023) / 1024, 1024>>>(Wq, Wv, bq, bv);
    // 2) MT[v,q] = sum_h Wv[h,v] * Wq[h,q]  -> fp16 directly
    gemm_tn_kernel<<<dim3(QD / 128, VD / 128, 1), 256>>>(Wv, Wq, pMTf, HIDD, VD, QD, QD);
    // 3) fused convert + row-dot for Q (needed by GEMM1)
    fuse_cvt_dot<QD, QD / 128, true><<<(B_ * NQ) / 8, 256>>>(Q, pQf, pa, prq);
    // 4) QM = Q @ MT^T   (4th launch -> gets the ncu capture)
    mma_gemm<false><<<dim3(VD / 128, (B_ * NQ) / 128, 1), 256, SMEM_DYN>>>(
        pQf, pMTf, QD, 0, 0, pQMf, VD, nullptr, nullptr, nullptr, nullptr, nullptr);
    // 5) fused convert + row-dot for V
    fuse_cvt_dot<VD, VD / 128, false><<<(B_ * NV) / 8, 256>>>(V, pVf, pc, pcv);
    // 6) E = exp(tanh(QM @ V^T + rq + cv)) -> fp16, + fused row/col sums
    mma_gemm<true><<<dim3(NV / 128, NQ / 128, B_), 256, SMEM_DYN>>>(
        pQMf, pVf, VD, (long long)NQ * VD, (long long)NV * VD,
        nullptr, 0, pE, prq, pcv, pdr, pdc);
    // 7) fused wq + wv (one pass over E)
    wqwv_kernel<<<dim3(NQ / 128, B_), 256>>>(pdr, pdc, pwv);
    // 8) pools (4-way parallel, atomic partials)
    vhat_kernel<<<dim3(B_, 4), VD>>>(pwv, pvh);
    qhat_kernel<<<dim3(B_, 4), QD>>>(pqh);
    // 9) writeout
    writeout_kernel<<<(B_ * VD + B_ * QD + 255) / 256, 256>>>(pvh, pqh, out);
}